// round 10
// baseline (speedup 1.0000x reference)
#include <cuda_runtime.h>
#include <cuda_bf16.h>
#include <cstdint>

#define Dd 16
#define BATCH 32768

typedef unsigned long long ull;

#define NT 5   // distinct t values

// -------- tangent-kernel constants (validated R8/R9) --------
#define TF_STRIDE 68
#define TF_M3T    (16 * TF_STRIDE)
#define TF_FLOATS (2 * 16 * TF_STRIDE)
#define BP_STRIDE 72
#define BP_ELEMS  (64 * BP_STRIDE)

// -------- forward-kernel bf16 weight planes (per t), element offsets --------
#define FB_W0H 0
#define FB_W0L 1152
#define FB_W1H 2304
#define FB_W1L 6912
#define FB_W2H 11520
#define FB_W2L 16128
#define FB_W3H 20736
#define FB_W3L 22272
#define FB_BF  23808
#define FB_BYTES_BF (FB_BF * 2)           // 47616
#define FB_CF  208
// per-warp d-stage: 16 rows x stride 68 floats
#define STG_STRIDE 68
#define STG_WARP   (16 * STG_STRIDE)      // 1088 floats
#define FWD_SMEM (FB_BYTES_BF + FB_CF * 4 + 4 * STG_WARP * 4)

__device__ __align__(16) float g_Tf[NT * TF_FLOATS];
__device__ __align__(16) __nv_bfloat16 g_Tbf[NT * 4 * BP_ELEMS];
__device__ __align__(16) __nv_bfloat16 g_FWb[NT * FB_BF];
__device__ __align__(16) float g_FWc[NT * FB_CF];
__device__ float g_d[8ull * BATCH * 192];
__device__ float g_dl[8 * BATCH];

__device__ __forceinline__ float sigm(float x) {
    return __fdividef(1.f, 1.f + __expf(-x));
}
__device__ __forceinline__ float tanh_f(float x) {
    x = fminf(fmaxf(x, -15.f), 15.f);
    float e = __expf(-2.f * x);
    return __fdividef(1.f - e, 1.f + e);
}
__device__ __forceinline__ uint32_t smem_u32(const void* p) {
    uint32_t a;
    asm("{ .reg .u64 t; cvta.to.shared.u64 t, %1; cvt.u32.u64 %0, t; }" : "=r"(a) : "l"(p));
    return a;
}
__device__ __forceinline__ uint32_t bf2_split(float v0, float v1, uint32_t& lo) {
    uint32_t h;
    asm("cvt.rn.bf16x2.f32 %0, %1, %2;" : "=r"(h) : "f"(v1), "f"(v0));
    float r0 = v0 - __uint_as_float(h << 16);
    float r1 = v1 - __uint_as_float(h & 0xFFFF0000u);
    asm("cvt.rn.bf16x2.f32 %0, %1, %2;" : "=r"(lo) : "f"(r1), "f"(r0));
    return h;
}
__device__ __forceinline__ void ldmx4(uint32_t addr, uint32_t& r0, uint32_t& r1,
                                      uint32_t& r2, uint32_t& r3) {
    asm volatile("ldmatrix.sync.aligned.m8n8.x4.trans.shared.b16 {%0,%1,%2,%3}, [%4];"
                 : "=r"(r0), "=r"(r1), "=r"(r2), "=r"(r3) : "r"(addr));
}
__device__ __forceinline__ void mma16816(float* c, const uint32_t* a, uint32_t b0, uint32_t b1) {
    asm("mma.sync.aligned.m16n8k16.row.col.f32.bf16.bf16.f32 "
        "{%0,%1,%2,%3}, {%4,%5,%6,%7}, {%8,%9}, {%0,%1,%2,%3};"
        : "+f"(c[0]), "+f"(c[1]), "+f"(c[2]), "+f"(c[3])
        : "r"(a[0]), "r"(a[1]), "r"(a[2]), "r"(a[3]), "r"(b0), "r"(b1));
}
__device__ __forceinline__ void mma3(float* c, const uint32_t* ah, const uint32_t* al,
                                     uint32_t bh0, uint32_t bh1, uint32_t bl0, uint32_t bl1) {
    mma16816(c, ah, bh0, bh1);
    mma16816(c, al, bh0, bh1);
    mma16816(c, ah, bl0, bl1);
}

// ---------------- build kernel ----------------
__global__ void build_kernel(const float* __restrict__ ts,
    const float* __restrict__ W0, const float* __restrict__ b0, const float* __restrict__ g0, const float* __restrict__ gb0, const float* __restrict__ hb0,
    const float* __restrict__ W1, const float* __restrict__ b1, const float* __restrict__ g1, const float* __restrict__ gb1, const float* __restrict__ hb1,
    const float* __restrict__ W2, const float* __restrict__ b2, const float* __restrict__ g2, const float* __restrict__ gb2, const float* __restrict__ hb2,
    const float* __restrict__ W3, const float* __restrict__ b3, const float* __restrict__ g3, const float* __restrict__ gb3, const float* __restrict__ hb3)
{
    const int tt = blockIdx.x;
    const float ts0 = ts[0], ts1 = ts[1], ts2 = ts[2];
    float t;
    if (tt == 0) t = ts0;
    else if (tt == 1) t = ts0 + 0.5f * (ts1 - ts0);
    else if (tt == 2) t = ts1;
    else if (tt == 3) t = ts1 + 0.5f * (ts2 - ts1);
    else t = ts2;

    float* tf = g_Tf + tt * TF_FLOATS;
    __nv_bfloat16* bp = g_Tbf + (size_t)tt * 4 * BP_ELEMS;
    __nv_bfloat16* fw = g_FWb + (size_t)tt * FB_BF;
    float* fc = g_FWc + tt * FB_CF;
    const int tid = threadIdx.x;

    for (int i = tid; i < 1024; i += blockDim.x) {
        int j = i >> 6, c = i & 63;
        float v = W0[i] * sigm(t * g0[c] + gb0[c]);
        tf[j * TF_STRIDE + c] = v;
        __nv_bfloat16 h = __float2bfloat16_rn(v);
        __nv_bfloat16 l = __float2bfloat16_rn(v - __bfloat162float(h));
        fw[FB_W0H + j * 72 + c] = h;
        fw[FB_W0L + j * 72 + c] = l;
    }
    for (int i = tid; i < 4096; i += blockDim.x) {
        int a = i >> 6, b = i & 63;
        float v = W1[i] * sigm(t * g1[b] + gb1[b]);
        __nv_bfloat16 h = __float2bfloat16_rn(v);
        __nv_bfloat16 l = __float2bfloat16_rn(v - __bfloat162float(h));
        bp[0 * BP_ELEMS + a * BP_STRIDE + b] = h;
        bp[1 * BP_ELEMS + a * BP_STRIDE + b] = l;
        fw[FB_W1H + a * 72 + b] = h;
        fw[FB_W1L + a * 72 + b] = l;
    }
    for (int i = tid; i < 4096; i += blockDim.x) {
        int b = i >> 6, c = i & 63;
        float v = W2[i] * sigm(t * g2[c] + gb2[c]);
        __nv_bfloat16 h = __float2bfloat16_rn(v);
        __nv_bfloat16 l = __float2bfloat16_rn(v - __bfloat162float(h));
        bp[2 * BP_ELEMS + c * BP_STRIDE + b] = h;
        bp[3 * BP_ELEMS + c * BP_STRIDE + b] = l;
        fw[FB_W2H + b * 72 + c] = h;
        fw[FB_W2L + b * 72 + c] = l;
    }
    for (int i = tid; i < 1024; i += blockDim.x) {
        int j = i >> 4, e = i & 15;
        float v = W3[i] * sigm(t * g3[e] + gb3[e]);
        tf[TF_M3T + e * TF_STRIDE + j] = v;
        __nv_bfloat16 h = __float2bfloat16_rn(v);
        __nv_bfloat16 l = __float2bfloat16_rn(v - __bfloat162float(h));
        fw[FB_W3H + j * 24 + e] = h;
        fw[FB_W3L + j * 24 + e] = l;
    }
    if (tid < 64) {
        float s0 = sigm(t * g0[tid] + gb0[tid]);
        float s1 = sigm(t * g1[tid] + gb1[tid]);
        float s2 = sigm(t * g2[tid] + gb2[tid]);
        fc[0 + tid]   = b0[tid] * s0 + t * hb0[tid];
        fc[64 + tid]  = b1[tid] * s1 + t * hb1[tid];
        fc[128 + tid] = b2[tid] * s2 + t * hb2[tid];
        if (tid < 16) {
            float s3 = sigm(t * g3[tid] + gb3[tid]);
            fc[192 + tid] = b3[tid] * s3 + t * hb3[tid];
        }
    }
}

// ================= forward kernel =================
// epilogue: bias+tanh, d's into smem stage (stride-68 rows), repack A fragments
__device__ __forceinline__ void fwd_epi(const float* acc, const float* Cv,
                                        float* stg, int g, int tig,
                                        uint32_t* fh, uint32_t* fl)
{
    #pragma unroll
    for (int nt = 0; nt < 8; ++nt) {
        const int col = nt * 8 + 2 * tig;
        const float b0 = Cv[col], b1 = Cv[col + 1];
        const float h0 = tanh_f(acc[nt * 4 + 0] + b0);
        const float h1 = tanh_f(acc[nt * 4 + 1] + b1);
        const float h2 = tanh_f(acc[nt * 4 + 2] + b0);
        const float h3 = tanh_f(acc[nt * 4 + 3] + b1);
        *(float2*)(stg + g * STG_STRIDE + col)       = make_float2(1.f - h0 * h0, 1.f - h1 * h1);
        *(float2*)(stg + (g + 8) * STG_STRIDE + col) = make_float2(1.f - h2 * h2, 1.f - h3 * h3);
        const int kk = nt >> 1, hf = nt & 1;
        fh[kk * 4 + hf * 2 + 0] = bf2_split(h0, h1, fl[kk * 4 + hf * 2 + 0]);
        fh[kk * 4 + hf * 2 + 1] = bf2_split(h2, h3, fl[kk * 4 + hf * 2 + 1]);
    }
}

// coalesced stage -> g_d flush: 16 rows x 64 floats, dst row stride 192
__device__ __forceinline__ void stage_flush(const float* stg, float* dst, int lane)
{
    #pragma unroll
    for (int k = 0; k < 8; ++k) {
        const int idx4 = lane + k * 32;
        const int row = idx4 >> 4, c4 = idx4 & 15;
        *(float4*)(dst + row * 192 + c4 * 4) = *(const float4*)(stg + row * STG_STRIDE + c4 * 4);
    }
}

__global__ __launch_bounds__(128, 3)
void forward_kernel(const float* __restrict__ ts, const float* __restrict__ x0,
                    float* __restrict__ out)
{
    extern __shared__ char smc[];
    float* C = (float*)(smc + FB_BYTES_BF);
    float* stage = (float*)(smc + FB_BYTES_BF + FB_CF * 4);

    const int tid  = threadIdx.x;
    const int lane = tid & 31;
    const int wid  = tid >> 5;
    const int g = lane >> 2, tig = lane & 3;
    const int d0c = 2 * tig, d1c = 8 + 2 * tig;

    float* stg = stage + wid * STG_WARP;
    const int rowbase = blockIdx.x * 64 + wid * 16;
    const int rowA = rowbase + g;
    const int rowB = rowA + 8;

    const uint32_t smb = smem_u32(smc);
    const uint32_t lrow = lane & 15, lcol = (lane >> 4) * 16;

    const float ts0 = ts[0], ts1 = ts[1], ts2 = ts[2];
    const float tst[3] = {ts0, ts1, ts2};

    float xs[8];
    {
        float2 p0 = *(const float2*)(x0 + rowA * 16 + d0c);
        float2 p1 = *(const float2*)(x0 + rowB * 16 + d0c);
        float2 p2 = *(const float2*)(x0 + rowA * 16 + d1c);
        float2 p3 = *(const float2*)(x0 + rowB * 16 + d1c);
        xs[0] = p0.x; xs[1] = p0.y; xs[2] = p1.x; xs[3] = p1.y;
        xs[4] = p2.x; xs[5] = p2.y; xs[6] = p3.x; xs[7] = p3.y;
        *(float2*)(out + rowA * 16 + d0c) = p0;
        *(float2*)(out + rowB * 16 + d0c) = p1;
        *(float2*)(out + rowA * 16 + d1c) = p2;
        *(float2*)(out + rowB * 16 + d1c) = p3;
    }
    float vA = 0.f, vB = 0.f;
    int ptt = -1;

    #pragma unroll 1
    for (int step = 0; step < 2; ++step) {
        const float tA = tst[step];
        const float hstep = tst[step + 1] - tA;
        float ksx[8], kxp[8];
        #pragma unroll
        for (int i = 0; i < 8; ++i) { ksx[i] = 0.f; kxp[i] = 0.f; }
        float ksvA = 0.f, ksvB = 0.f;

        #pragma unroll 1
        for (int stage_i = 0; stage_i < 4; ++stage_i) {
            const int tt = step * 2 + ((stage_i == 0) ? 0 : ((stage_i == 3) ? 2 : 1));
            if (tt != ptt) {
                __syncthreads();
                const uint4* src = (const uint4*)(g_FWb + (size_t)tt * FB_BF);
                uint4* dst = (uint4*)smc;
                #pragma unroll 1
                for (int i = tid; i < FB_BYTES_BF / 16; i += 128) dst[i] = __ldg(src + i);
                const uint4* cs = (const uint4*)(g_FWc + tt * FB_CF);
                uint4* cd = (uint4*)(smc + FB_BYTES_BF);
                if (tid < FB_CF / 4) cd[tid] = __ldg(cs + tid);
                __syncthreads();
                ptt = tt;
            }
            const int e = step * 4 + stage_i;
            const float coef = (stage_i == 0) ? 0.f : ((stage_i == 3) ? hstep : 0.5f * hstep);
            const float wq = (stage_i == 1 || stage_i == 2) ? 2.f : 1.f;

            float* gdw = g_d + ((size_t)e * BATCH + rowbase) * 192;

            // ---- L0 A-frags from state regs ----
            uint32_t fh[16], fl[16];
            {
                float xe[8];
                #pragma unroll
                for (int i = 0; i < 8; ++i) xe[i] = xs[i] + coef * kxp[i];
                fh[0] = bf2_split(xe[0], xe[1], fl[0]);
                fh[1] = bf2_split(xe[2], xe[3], fl[1]);
                fh[2] = bf2_split(xe[4], xe[5], fl[2]);
                fh[3] = bf2_split(xe[6], xe[7], fl[3]);
            }
            float acc[32];

            // ---- L0: k=16 ----
            #pragma unroll
            for (int i = 0; i < 32; ++i) acc[i] = 0.f;
            {
                const uint32_t rb_ = smb + FB_W0H * 2 + lrow * 144 + lcol;
                #pragma unroll
                for (int p = 0; p < 4; ++p) {
                    uint32_t h0, h1, h2, h3, l0, l1, l2, l3;
                    ldmx4(rb_ + p * 32, h0, h1, h2, h3);
                    ldmx4(rb_ + p * 32 + 2304, l0, l1, l2, l3);
                    mma3(acc + (2 * p) * 4, fh, fl, h0, h1, l0, l1);
                    mma3(acc + (2 * p + 1) * 4, fh, fl, h2, h3, l2, l3);
                }
            }
            fwd_epi(acc, C + 0, stg, g, tig, fh, fl);
            __syncwarp();
            stage_flush(stg, gdw + 0, lane);
            __syncwarp();

            // ---- L1: k=64 ----
            #pragma unroll
            for (int i = 0; i < 32; ++i) acc[i] = 0.f;
            {
                const uint32_t rb_ = smb + FB_W1H * 2 + lrow * 144 + lcol;
                #pragma unroll
                for (int kk = 0; kk < 4; ++kk) {
                    const uint32_t rk = rb_ + kk * 16 * 144;
                    #pragma unroll
                    for (int p = 0; p < 4; ++p) {
                        uint32_t h0, h1, h2, h3, l0, l1, l2, l3;
                        ldmx4(rk + p * 32, h0, h1, h2, h3);
                        ldmx4(rk + p * 32 + 9216, l0, l1, l2, l3);
                        mma3(acc + (2 * p) * 4, fh + kk * 4, fl + kk * 4, h0, h1, l0, l1);
                        mma3(acc + (2 * p + 1) * 4, fh + kk * 4, fl + kk * 4, h2, h3, l2, l3);
                    }
                }
            }
            fwd_epi(acc, C + 64, stg, g, tig, fh, fl);
            __syncwarp();
            stage_flush(stg, gdw + 64, lane);
            __syncwarp();

            // ---- L2: k=64 ----
            #pragma unroll
            for (int i = 0; i < 32; ++i) acc[i] = 0.f;
            {
                const uint32_t rb_ = smb + FB_W2H * 2 + lrow * 144 + lcol;
                #pragma unroll
                for (int kk = 0; kk < 4; ++kk) {
                    const uint32_t rk = rb_ + kk * 16 * 144;
                    #pragma unroll
                    for (int p = 0; p < 4; ++p) {
                        uint32_t h0, h1, h2, h3, l0, l1, l2, l3;
                        ldmx4(rk + p * 32, h0, h1, h2, h3);
                        ldmx4(rk + p * 32 + 9216, l0, l1, l2, l3);
                        mma3(acc + (2 * p) * 4, fh + kk * 4, fl + kk * 4, h0, h1, l0, l1);
                        mma3(acc + (2 * p + 1) * 4, fh + kk * 4, fl + kk * 4, h2, h3, l2, l3);
                    }
                }
            }
            fwd_epi(acc, C + 128, stg, g, tig, fh, fl);
            __syncwarp();
            stage_flush(stg, gdw + 128, lane);
            __syncwarp();

            // ---- L3: k=64, n=16, no tanh ----
            float a3[8];
            #pragma unroll
            for (int i = 0; i < 8; ++i) a3[i] = 0.f;
            {
                const uint32_t rb_ = smb + FB_W3H * 2 + lrow * 48 + lcol;
                #pragma unroll
                for (int kk = 0; kk < 4; ++kk) {
                    uint32_t h0, h1, h2, h3, l0, l1, l2, l3;
                    ldmx4(rb_ + kk * 16 * 48, h0, h1, h2, h3);
                    ldmx4(rb_ + kk * 16 * 48 + 3072, l0, l1, l2, l3);
                    mma3(a3 + 0, fh + kk * 4, fl + kk * 4, h0, h1, l0, l1);
                    mma3(a3 + 4, fh + kk * 4, fl + kk * 4, h2, h3, l2, l3);
                }
            }
            float dxv[8];
            dxv[0] = a3[0] + C[192 + d0c];  dxv[1] = a3[1] + C[192 + d0c + 1];
            dxv[2] = a3[2] + C[192 + d0c];  dxv[3] = a3[3] + C[192 + d0c + 1];
            dxv[4] = a3[4] + C[192 + d1c];  dxv[5] = a3[5] + C[192 + d1c + 1];
            dxv[6] = a3[6] + C[192 + d1c];  dxv[7] = a3[7] + C[192 + d1c + 1];

            float dvA = dxv[0] * dxv[0] + dxv[1] * dxv[1] + dxv[4] * dxv[4] + dxv[5] * dxv[5];
            float dvB = dxv[2] * dxv[2] + dxv[3] * dxv[3] + dxv[6] * dxv[6] + dxv[7] * dxv[7];
            dvA += __shfl_xor_sync(0xffffffffu, dvA, 1);
            dvA += __shfl_xor_sync(0xffffffffu, dvA, 2);
            dvB += __shfl_xor_sync(0xffffffffu, dvB, 1);
            dvB += __shfl_xor_sync(0xffffffffu, dvB, 2);

            #pragma unroll
            for (int i = 0; i < 8; ++i) { ksx[i] += wq * dxv[i]; kxp[i] = dxv[i]; }
            ksvA += wq * dvA;
            ksvB += wq * dvB;
        }

        const float scl = hstep * (1.f / 6.f);
        #pragma unroll
        for (int i = 0; i < 8; ++i) xs[i] += scl * ksx[i];
        vA += scl * 0.5f * ksvA;
        vB += scl * 0.5f * ksvB;

        float* os = out + (step + 1) * BATCH * Dd;
        *(float2*)(os + rowA * 16 + d0c) = make_float2(xs[0], xs[1]);
        *(float2*)(os + rowB * 16 + d0c) = make_float2(xs[2], xs[3]);
        *(float2*)(os + rowA * 16 + d1c) = make_float2(xs[4], xs[5]);
        *(float2*)(os + rowB * 16 + d1c) = make_float2(xs[6], xs[7]);
    }

    if (tig == 0) {
        const int base = 3 * BATCH * Dd;
        out[base + BATCH + rowA] = fabsf(vA);
        out[base + BATCH + rowB] = fabsf(vB);
        out[base + 2 * BATCH + rowA] = 0.f;
        out[base + 2 * BATCH + rowB] = 0.f;
    }
}

// ================= tangent kernel (64 rows/CTA) =================
#define TS_TF 9216
#define TS_DV (TS_TF + TF_FLOATS)
#define TS_FLOATS (TS_DV + 64 * 192)
#define TS_BYTES (TS_FLOATS * 4)

__global__ __launch_bounds__(256, 2)
void tangent_kernel()
{
    extern __shared__ float sm[];
    const int tid = threadIdx.x;
    const int lane = tid & 31;
    const int wid = tid >> 5;

    const int e = blockIdx.x >> 9;        // 0..7
    const int rg = blockIdx.x & 511;      // 0..511
    const int row0 = rg * 64;
    const int tmap[8] = {0, 1, 1, 2, 2, 3, 3, 4};
    const int tt = tmap[e];

    {
        const uint4* bsrc = (const uint4*)(g_Tbf + (size_t)tt * 4 * BP_ELEMS);
        uint4* bdst = (uint4*)sm;
        #pragma unroll 1
        for (int i = tid; i < (4 * BP_ELEMS * 2) / 16; i += 256) bdst[i] = __ldg(bsrc + i);
        const uint4* fsrc = (const uint4*)(g_Tf + tt * TF_FLOATS);
        uint4* fdst = (uint4*)(sm + TS_TF);
        #pragma unroll 1
        for (int i = tid; i < TF_FLOATS / 4; i += 256) fdst[i] = __ldg(fsrc + i);
        const uint4* dsrc = (const uint4*)(g_d + ((size_t)e * BATCH + row0) * 192);
        uint4* ddst = (uint4*)(sm + TS_DV);
        #pragma unroll 1
        for (int i = tid; i < (64 * 192) / 4; i += 256) ddst[i] = __ldg(dsrc + i);
    }
    __syncthreads();

    const uint32_t smbB = smem_u32(sm);
    const float* M0f = sm + TS_TF;
    const float* M3T = sm + TS_TF + TF_M3T;

    const int g = lane >> 2;
    const int k0 = (lane & 3) * 2;
    const uint32_t lrow = lane & 15, lcol = (lane >> 4) * 16;

    #pragma unroll 1
    for (int rl = 0; rl < 8; ++rl) {
        const int r = wid * 8 + rl;
        const float* d0p = sm + TS_DV + r * 192;
        const float* d1p = d0p + 64;
        const float* d2p = d0p + 128;

        float acc1[32], acc2[32];
        #pragma unroll
        for (int i = 0; i < 32; ++i) { acc1[i] = 0.f; acc2[i] = 0.f; }

        // ---- GEMM1: U2 = (M0f .* d0) @ B1 ----
        #pragma unroll
        for (int kk = 0; kk < 4; ++kk) {
            const int K = kk * 16;
            const float2 dA = *(const float2*)(d0p + K + k0);
            const float2 dB = *(const float2*)(d0p + K + k0 + 8);
            const float2 mA = *(const float2*)(M0f + g * TF_STRIDE + K + k0);
            const float2 mB = *(const float2*)(M0f + (g + 8) * TF_STRIDE + K + k0);
            const float2 mC = *(const float2*)(M0f + g * TF_STRIDE + K + k0 + 8);
            const float2 mD = *(const float2*)(M0f + (g + 8) * TF_STRIDE + K + k0 + 8);
            uint32_t ah[4], al[4];
            ah[0] = bf2_split(mA.x * dA.x, mA.y * dA.y, al[0]);
            ah[1] = bf2_split(mB.x * dA.x, mB.y * dA.y, al[1]);
            ah[2] = bf2_split(mC.x * dB.x, mC.y * dB.y, al[2]);
            ah[3] = bf2_split(mD.x * dB.x, mD.y * dB.y, al[3]);
            const uint32_t rowaddr = smbB + (K + lrow) * (BP_STRIDE * 2) + lcol;
            #pragma unroll
            for (int p = 0; p < 4; ++p) {
                uint32_t h0, h1, h2, h3, l0, l1, l2, l3;
                ldmx4(rowaddr + p * 32, h0, h1, h2, h3);
                ldmx4(rowaddr + p * 32 + BP_ELEMS * 2, l0, l1, l2, l3);
                mma3(acc1 + (2 * p) * 4, ah, al, h0, h1, l0, l1);
                mma3(acc1 + (2 * p + 1) * 4, ah, al, h2, h3, l2, l3);
            }
        }

        // ---- GEMM2: W = (M3T .* d2) @ B2 ----
        #pragma unroll
        for (int kk = 0; kk < 4; ++kk) {
            const int K = kk * 16;
            const float2 dA = *(const float2*)(d2p + K + k0);
            const float2 dB = *(const float2*)(d2p + K + k0 + 8);
            const float2 mA = *(const float2*)(M3T + g * TF_STRIDE + K + k0);
            const float2 mB = *(const float2*)(M3T + (g + 8) * TF_STRIDE + K + k0);
            const float2 mC = *(const float2*)(M3T + g * TF_STRIDE + K + k0 + 8);
            const float2 mD = *(const float2*)(M3T + (g + 8) * TF_STRIDE + K + k0 + 8);
            uint32_t ah[4], al[4];
            ah[0] = bf2_split(mA.x * dA.x, mA.y * dA.y, al[0]);
            ah[1] = bf2_split(mB.x * dA.x, mB.y * dA.y, al[1]);
            ah[2] = bf2_split(mC.x * dB.x, mC.y * dB.y, al[2]);
            ah[3] = bf2_split(mD.x * dB.x, mD.y * dB.y, al[3]);
            const uint32_t rowaddr = smbB + (K + lrow) * (BP_STRIDE * 2) + lcol + 2 * BP_ELEMS * 2;
            #pragma unroll
            for (int p = 0; p < 4; ++p) {
                uint32_t h0, h1, h2, h3, l0, l1, l2, l3;
                ldmx4(rowaddr + p * 32, h0, h1, h2, h3);
                ldmx4(rowaddr + p * 32 + BP_ELEMS * 2, l0, l1, l2, l3);
                mma3(acc2 + (2 * p) * 4, ah, al, h0, h1, l0, l1);
                mma3(acc2 + (2 * p + 1) * 4, ah, al, h2, h3, l2, l3);
            }
        }

        // ---- dl = sum U2 .* d1 .* W ----
        float dl = 0.f;
        #pragma unroll
        for (int nt = 0; nt < 8; ++nt) {
            const float2 dp = *(const float2*)(d1p + nt * 8 + k0);
            dl = fmaf(acc1[nt * 4 + 0] * dp.x, acc2[nt * 4 + 0], dl);
            dl = fmaf(acc1[nt * 4 + 1] * dp.y, acc2[nt * 4 + 1], dl);
            dl = fmaf(acc1[nt * 4 + 2] * dp.x, acc2[nt * 4 + 2], dl);
            dl = fmaf(acc1[nt * 4 + 3] * dp.y, acc2[nt * 4 + 3], dl);
        }
        #pragma unroll
        for (int m = 1; m <= 16; m <<= 1)
            dl += __shfl_xor_sync(0xffffffffu, dl, m);
        if (lane == 0)
            g_dl[e * BATCH + row0 + r] = dl;
    }
}

// ================= combine kernel =================
__global__ void combine_kernel(const float* __restrict__ ts, float* __restrict__ out)
{
    const int r = blockIdx.x * 256 + threadIdx.x;
    const float h0 = ts[1] - ts[0], h1 = ts[2] - ts[1];
    const float* dl = g_dl;
    float l = (h0 * (1.f / 6.f)) * (dl[r] + 2.f * dl[BATCH + r] + 2.f * dl[2 * BATCH + r] + dl[3 * BATCH + r])
            + (h1 * (1.f / 6.f)) * (dl[4 * BATCH + r] + 2.f * dl[5 * BATCH + r] + 2.f * dl[6 * BATCH + r] + dl[7 * BATCH + r]);
    out[3 * BATCH * Dd + r] = l;
}

extern "C" void kernel_launch(void* const* d_in, const int* in_sizes, int n_in,
                              void* d_out, int out_size) {
    const float* ts  = (const float*)d_in[0];
    const float* x0  = (const float*)d_in[1];
    const float* W0  = (const float*)d_in[2];
    const float* b0  = (const float*)d_in[3];
    const float* g0  = (const float*)d_in[4];
    const float* gb0 = (const float*)d_in[5];
    const float* hb0 = (const float*)d_in[6];
    const float* W1  = (const float*)d_in[7];
    const float* b1  = (const float*)d_in[8];
    const float* g1  = (const float*)d_in[9];
    const float* gb1 = (const float*)d_in[10];
    const float* hb1 = (const float*)d_in[11];
    const float* W2  = (const float*)d_in[12];
    const float* b2  = (const float*)d_in[13];
    const float* g2  = (const float*)d_in[14];
    const float* gb2 = (const float*)d_in[15];
    const float* hb2 = (const float*)d_in[16];
    const float* W3  = (const float*)d_in[17];
    const float* b3  = (const float*)d_in[18];
    const float* g3  = (const float*)d_in[19];
    const float* gb3 = (const float*)d_in[20];
    const float* hb3 = (const float*)d_in[21];
    float* out = (float*)d_out;

    build_kernel<<<NT, 256>>>(ts,
        W0, b0, g0, gb0, hb0,
        W1, b1, g1, gb1, hb1,
        W2, b2, g2, gb2, hb2,
        W3, b3, g3, gb3, hb3);

    cudaFuncSetAttribute(forward_kernel, cudaFuncAttributeMaxDynamicSharedMemorySize, FWD_SMEM);
    forward_kernel<<<BATCH / 64, 128, FWD_SMEM>>>(ts, x0, out);

    cudaFuncSetAttribute(tangent_kernel, cudaFuncAttributeMaxDynamicSharedMemorySize, TS_BYTES);
    tangent_kernel<<<8 * 512, 256, TS_BYTES>>>();

    combine_kernel<<<BATCH / 256, 256>>>(ts, out);
}

// round 11
// speedup vs baseline: 1.2414x; 1.2414x over previous
#include <cuda_runtime.h>
#include <cuda_bf16.h>
#include <cuda_fp16.h>
#include <cstdint>

#define Dd 16
#define BATCH 32768

typedef unsigned long long ull;

#define NT 5   // distinct t values

// -------- tangent-kernel constants --------
#define TF_STRIDE 68
#define TF_M3T    (16 * TF_STRIDE)
#define TF_FLOATS (2 * 16 * TF_STRIDE)
#define BP_STRIDE 72
#define BP_ELEMS  (64 * BP_STRIDE)

// -------- forward-kernel bf16 weight planes (per t), element offsets --------
#define FB_W0H 0
#define FB_W0L 1152
#define FB_W1H 2304
#define FB_W1L 6912
#define FB_W2H 11520
#define FB_W2L 16128
#define FB_W3H 20736
#define FB_W3L 22272
#define FB_BF  23808
#define FB_BYTES_BF (FB_BF * 2)
#define FB_CF  208
#define STG_STRIDE 68
#define STG_WARP   (16 * STG_STRIDE)
#define FWD_SMEM (FB_BYTES_BF + FB_CF * 4 + 4 * STG_WARP * 4)

__device__ __align__(16) float g_Tf[NT * TF_FLOATS];
__device__ __align__(16) __half g_Thf[NT * 2 * BP_ELEMS];   // fp16 B planes: B1, B2
__device__ __align__(16) __nv_bfloat16 g_FWb[NT * FB_BF];
__device__ __align__(16) float g_FWc[NT * FB_CF];
__device__ float g_d[8ull * BATCH * 192];
__device__ float g_dl[8 * BATCH];

__device__ __forceinline__ float sigm(float x) {
    return __fdividef(1.f, 1.f + __expf(-x));
}
__device__ __forceinline__ float tanh_f(float x) {
    x = fminf(fmaxf(x, -15.f), 15.f);
    float e = __expf(-2.f * x);
    return __fdividef(1.f - e, 1.f + e);
}
__device__ __forceinline__ uint32_t smem_u32(const void* p) {
    uint32_t a;
    asm("{ .reg .u64 t; cvta.to.shared.u64 t, %1; cvt.u32.u64 %0, t; }" : "=r"(a) : "l"(p));
    return a;
}
__device__ __forceinline__ uint32_t bf2_split(float v0, float v1, uint32_t& lo) {
    uint32_t h;
    asm("cvt.rn.bf16x2.f32 %0, %1, %2;" : "=r"(h) : "f"(v1), "f"(v0));
    float r0 = v0 - __uint_as_float(h << 16);
    float r1 = v1 - __uint_as_float(h & 0xFFFF0000u);
    asm("cvt.rn.bf16x2.f32 %0, %1, %2;" : "=r"(lo) : "f"(r1), "f"(r0));
    return h;
}
__device__ __forceinline__ uint32_t f16pk(float v0, float v1) {
    uint32_t r;
    asm("cvt.rn.f16x2.f32 %0, %1, %2;" : "=r"(r) : "f"(v1), "f"(v0));
    return r;
}
__device__ __forceinline__ void ldmx4(uint32_t addr, uint32_t& r0, uint32_t& r1,
                                      uint32_t& r2, uint32_t& r3) {
    asm volatile("ldmatrix.sync.aligned.m8n8.x4.trans.shared.b16 {%0,%1,%2,%3}, [%4];"
                 : "=r"(r0), "=r"(r1), "=r"(r2), "=r"(r3) : "r"(addr));
}
__device__ __forceinline__ void mma16816(float* c, const uint32_t* a, uint32_t b0, uint32_t b1) {
    asm("mma.sync.aligned.m16n8k16.row.col.f32.bf16.bf16.f32 "
        "{%0,%1,%2,%3}, {%4,%5,%6,%7}, {%8,%9}, {%0,%1,%2,%3};"
        : "+f"(c[0]), "+f"(c[1]), "+f"(c[2]), "+f"(c[3])
        : "r"(a[0]), "r"(a[1]), "r"(a[2]), "r"(a[3]), "r"(b0), "r"(b1));
}
__device__ __forceinline__ void mma16816h(float* c, const uint32_t* a, uint32_t b0, uint32_t b1) {
    asm("mma.sync.aligned.m16n8k16.row.col.f32.f16.f16.f32 "
        "{%0,%1,%2,%3}, {%4,%5,%6,%7}, {%8,%9}, {%0,%1,%2,%3};"
        : "+f"(c[0]), "+f"(c[1]), "+f"(c[2]), "+f"(c[3])
        : "r"(a[0]), "r"(a[1]), "r"(a[2]), "r"(a[3]), "r"(b0), "r"(b1));
}
__device__ __forceinline__ void mma3(float* c, const uint32_t* ah, const uint32_t* al,
                                     uint32_t bh0, uint32_t bh1, uint32_t bl0, uint32_t bl1) {
    mma16816(c, ah, bh0, bh1);
    mma16816(c, al, bh0, bh1);
    mma16816(c, ah, bl0, bl1);
}

// ---------------- build kernel ----------------
__global__ void build_kernel(const float* __restrict__ ts,
    const float* __restrict__ W0, const float* __restrict__ b0, const float* __restrict__ g0, const float* __restrict__ gb0, const float* __restrict__ hb0,
    const float* __restrict__ W1, const float* __restrict__ b1, const float* __restrict__ g1, const float* __restrict__ gb1, const float* __restrict__ hb1,
    const float* __restrict__ W2, const float* __restrict__ b2, const float* __restrict__ g2, const float* __restrict__ gb2, const float* __restrict__ hb2,
    const float* __restrict__ W3, const float* __restrict__ b3, const float* __restrict__ g3, const float* __restrict__ gb3, const float* __restrict__ hb3)
{
    const int tt = blockIdx.x;
    const float ts0 = ts[0], ts1 = ts[1], ts2 = ts[2];
    float t;
    if (tt == 0) t = ts0;
    else if (tt == 1) t = ts0 + 0.5f * (ts1 - ts0);
    else if (tt == 2) t = ts1;
    else if (tt == 3) t = ts1 + 0.5f * (ts2 - ts1);
    else t = ts2;

    float* tf = g_Tf + tt * TF_FLOATS;
    __half* hp = g_Thf + (size_t)tt * 2 * BP_ELEMS;
    __nv_bfloat16* fw = g_FWb + (size_t)tt * FB_BF;
    float* fc = g_FWc + tt * FB_CF;
    const int tid = threadIdx.x;

    for (int i = tid; i < 1024; i += blockDim.x) {
        int j = i >> 6, c = i & 63;
        float v = W0[i] * sigm(t * g0[c] + gb0[c]);
        tf[j * TF_STRIDE + c] = v;
        __nv_bfloat16 h = __float2bfloat16_rn(v);
        __nv_bfloat16 l = __float2bfloat16_rn(v - __bfloat162float(h));
        fw[FB_W0H + j * 72 + c] = h;
        fw[FB_W0L + j * 72 + c] = l;
    }
    for (int i = tid; i < 4096; i += blockDim.x) {
        int a = i >> 6, b = i & 63;
        float v = W1[i] * sigm(t * g1[b] + gb1[b]);
        __nv_bfloat16 h = __float2bfloat16_rn(v);
        __nv_bfloat16 l = __float2bfloat16_rn(v - __bfloat162float(h));
        fw[FB_W1H + a * 72 + b] = h;
        fw[FB_W1L + a * 72 + b] = l;
        hp[0 * BP_ELEMS + a * BP_STRIDE + b] = __float2half_rn(v);   // tangent B1[k=a][n=b]
    }
    for (int i = tid; i < 4096; i += blockDim.x) {
        int b = i >> 6, c = i & 63;
        float v = W2[i] * sigm(t * g2[c] + gb2[c]);
        __nv_bfloat16 h = __float2bfloat16_rn(v);
        __nv_bfloat16 l = __float2bfloat16_rn(v - __bfloat162float(h));
        fw[FB_W2H + b * 72 + c] = h;
        fw[FB_W2L + b * 72 + c] = l;
        hp[1 * BP_ELEMS + c * BP_STRIDE + b] = __float2half_rn(v);   // tangent B2[k=c][n=b]
    }
    for (int i = tid; i < 1024; i += blockDim.x) {
        int j = i >> 4, e = i & 15;
        float v = W3[i] * sigm(t * g3[e] + gb3[e]);
        tf[TF_M3T + e * TF_STRIDE + j] = v;
        __nv_bfloat16 h = __float2bfloat16_rn(v);
        __nv_bfloat16 l = __float2bfloat16_rn(v - __bfloat162float(h));
        fw[FB_W3H + j * 24 + e] = h;
        fw[FB_W3L + j * 24 + e] = l;
    }
    if (tid < 64) {
        float s0 = sigm(t * g0[tid] + gb0[tid]);
        float s1 = sigm(t * g1[tid] + gb1[tid]);
        float s2 = sigm(t * g2[tid] + gb2[tid]);
        fc[0 + tid]   = b0[tid] * s0 + t * hb0[tid];
        fc[64 + tid]  = b1[tid] * s1 + t * hb1[tid];
        fc[128 + tid] = b2[tid] * s2 + t * hb2[tid];
        if (tid < 16) {
            float s3 = sigm(t * g3[tid] + gb3[tid]);
            fc[192 + tid] = b3[tid] * s3 + t * hb3[tid];
        }
    }
}

// ================= forward kernel (unchanged from R10) =================
__device__ __forceinline__ void fwd_epi(const float* acc, const float* Cv,
                                        float* stg, int g, int tig,
                                        uint32_t* fh, uint32_t* fl)
{
    #pragma unroll
    for (int nt = 0; nt < 8; ++nt) {
        const int col = nt * 8 + 2 * tig;
        const float b0 = Cv[col], b1 = Cv[col + 1];
        const float h0 = tanh_f(acc[nt * 4 + 0] + b0);
        const float h1 = tanh_f(acc[nt * 4 + 1] + b1);
        const float h2 = tanh_f(acc[nt * 4 + 2] + b0);
        const float h3 = tanh_f(acc[nt * 4 + 3] + b1);
        *(float2*)(stg + g * STG_STRIDE + col)       = make_float2(1.f - h0 * h0, 1.f - h1 * h1);
        *(float2*)(stg + (g + 8) * STG_STRIDE + col) = make_float2(1.f - h2 * h2, 1.f - h3 * h3);
        const int kk = nt >> 1, hf = nt & 1;
        fh[kk * 4 + hf * 2 + 0] = bf2_split(h0, h1, fl[kk * 4 + hf * 2 + 0]);
        fh[kk * 4 + hf * 2 + 1] = bf2_split(h2, h3, fl[kk * 4 + hf * 2 + 1]);
    }
}

__device__ __forceinline__ void stage_flush(const float* stg, float* dst, int lane)
{
    #pragma unroll
    for (int k = 0; k < 8; ++k) {
        const int idx4 = lane + k * 32;
        const int row = idx4 >> 4, c4 = idx4 & 15;
        *(float4*)(dst + row * 192 + c4 * 4) = *(const float4*)(stg + row * STG_STRIDE + c4 * 4);
    }
}

__global__ __launch_bounds__(128, 3)
void forward_kernel(const float* __restrict__ ts, const float* __restrict__ x0,
                    float* __restrict__ out)
{
    extern __shared__ char smc[];
    float* C = (float*)(smc + FB_BYTES_BF);
    float* stage = (float*)(smc + FB_BYTES_BF + FB_CF * 4);

    const int tid  = threadIdx.x;
    const int lane = tid & 31;
    const int wid  = tid >> 5;
    const int g = lane >> 2, tig = lane & 3;
    const int d0c = 2 * tig, d1c = 8 + 2 * tig;

    float* stg = stage + wid * STG_WARP;
    const int rowbase = blockIdx.x * 64 + wid * 16;
    const int rowA = rowbase + g;
    const int rowB = rowA + 8;

    const uint32_t smb = smem_u32(smc);
    const uint32_t lrow = lane & 15, lcol = (lane >> 4) * 16;

    const float ts0 = ts[0], ts1 = ts[1], ts2 = ts[2];
    const float tst[3] = {ts0, ts1, ts2};

    float xs[8];
    {
        float2 p0 = *(const float2*)(x0 + rowA * 16 + d0c);
        float2 p1 = *(const float2*)(x0 + rowB * 16 + d0c);
        float2 p2 = *(const float2*)(x0 + rowA * 16 + d1c);
        float2 p3 = *(const float2*)(x0 + rowB * 16 + d1c);
        xs[0] = p0.x; xs[1] = p0.y; xs[2] = p1.x; xs[3] = p1.y;
        xs[4] = p2.x; xs[5] = p2.y; xs[6] = p3.x; xs[7] = p3.y;
        *(float2*)(out + rowA * 16 + d0c) = p0;
        *(float2*)(out + rowB * 16 + d0c) = p1;
        *(float2*)(out + rowA * 16 + d1c) = p2;
        *(float2*)(out + rowB * 16 + d1c) = p3;
    }
    float vA = 0.f, vB = 0.f;
    int ptt = -1;

    #pragma unroll 1
    for (int step = 0; step < 2; ++step) {
        const float tA = tst[step];
        const float hstep = tst[step + 1] - tA;
        float ksx[8], kxp[8];
        #pragma unroll
        for (int i = 0; i < 8; ++i) { ksx[i] = 0.f; kxp[i] = 0.f; }
        float ksvA = 0.f, ksvB = 0.f;

        #pragma unroll 1
        for (int stage_i = 0; stage_i < 4; ++stage_i) {
            const int tt = step * 2 + ((stage_i == 0) ? 0 : ((stage_i == 3) ? 2 : 1));
            if (tt != ptt) {
                __syncthreads();
                const uint4* src = (const uint4*)(g_FWb + (size_t)tt * FB_BF);
                uint4* dst = (uint4*)smc;
                #pragma unroll 1
                for (int i = tid; i < FB_BYTES_BF / 16; i += 128) dst[i] = __ldg(src + i);
                const uint4* cs = (const uint4*)(g_FWc + tt * FB_CF);
                uint4* cd = (uint4*)(smc + FB_BYTES_BF);
                if (tid < FB_CF / 4) cd[tid] = __ldg(cs + tid);
                __syncthreads();
                ptt = tt;
            }
            const int e = step * 4 + stage_i;
            const float coef = (stage_i == 0) ? 0.f : ((stage_i == 3) ? hstep : 0.5f * hstep);
            const float wq = (stage_i == 1 || stage_i == 2) ? 2.f : 1.f;

            float* gdw = g_d + ((size_t)e * BATCH + rowbase) * 192;

            uint32_t fh[16], fl[16];
            {
                float xe[8];
                #pragma unroll
                for (int i = 0; i < 8; ++i) xe[i] = xs[i] + coef * kxp[i];
                fh[0] = bf2_split(xe[0], xe[1], fl[0]);
                fh[1] = bf2_split(xe[2], xe[3], fl[1]);
                fh[2] = bf2_split(xe[4], xe[5], fl[2]);
                fh[3] = bf2_split(xe[6], xe[7], fl[3]);
            }
            float acc[32];

            // ---- L0 ----
            #pragma unroll
            for (int i = 0; i < 32; ++i) acc[i] = 0.f;
            {
                const uint32_t rb_ = smb + FB_W0H * 2 + lrow * 144 + lcol;
                #pragma unroll
                for (int p = 0; p < 4; ++p) {
                    uint32_t h0, h1, h2, h3, l0, l1, l2, l3;
                    ldmx4(rb_ + p * 32, h0, h1, h2, h3);
                    ldmx4(rb_ + p * 32 + 2304, l0, l1, l2, l3);
                    mma3(acc + (2 * p) * 4, fh, fl, h0, h1, l0, l1);
                    mma3(acc + (2 * p + 1) * 4, fh, fl, h2, h3, l2, l3);
                }
            }
            fwd_epi(acc, C + 0, stg, g, tig, fh, fl);
            __syncwarp();
            stage_flush(stg, gdw + 0, lane);
            __syncwarp();

            // ---- L1 ----
            #pragma unroll
            for (int i = 0; i < 32; ++i) acc[i] = 0.f;
            {
                const uint32_t rb_ = smb + FB_W1H * 2 + lrow * 144 + lcol;
                #pragma unroll
                for (int kk = 0; kk < 4; ++kk) {
                    const uint32_t rk = rb_ + kk * 16 * 144;
                    #pragma unroll
                    for (int p = 0; p < 4; ++p) {
                        uint32_t h0, h1, h2, h3, l0, l1, l2, l3;
                        ldmx4(rk + p * 32, h0, h1, h2, h3);
                        ldmx4(rk + p * 32 + 9216, l0, l1, l2, l3);
                        mma3(acc + (2 * p) * 4, fh + kk * 4, fl + kk * 4, h0, h1, l0, l1);
                        mma3(acc + (2 * p + 1) * 4, fh + kk * 4, fl + kk * 4, h2, h3, l2, l3);
                    }
                }
            }
            fwd_epi(acc, C + 64, stg, g, tig, fh, fl);
            __syncwarp();
            stage_flush(stg, gdw + 64, lane);
            __syncwarp();

            // ---- L2 ----
            #pragma unroll
            for (int i = 0; i < 32; ++i) acc[i] = 0.f;
            {
                const uint32_t rb_ = smb + FB_W2H * 2 + lrow * 144 + lcol;
                #pragma unroll
                for (int kk = 0; kk < 4; ++kk) {
                    const uint32_t rk = rb_ + kk * 16 * 144;
                    #pragma unroll
                    for (int p = 0; p < 4; ++p) {
                        uint32_t h0, h1, h2, h3, l0, l1, l2, l3;
                        ldmx4(rk + p * 32, h0, h1, h2, h3);
                        ldmx4(rk + p * 32 + 9216, l0, l1, l2, l3);
                        mma3(acc + (2 * p) * 4, fh + kk * 4, fl + kk * 4, h0, h1, l0, l1);
                        mma3(acc + (2 * p + 1) * 4, fh + kk * 4, fl + kk * 4, h2, h3, l2, l3);
                    }
                }
            }
            fwd_epi(acc, C + 128, stg, g, tig, fh, fl);
            __syncwarp();
            stage_flush(stg, gdw + 128, lane);
            __syncwarp();

            // ---- L3 ----
            float a3[8];
            #pragma unroll
            for (int i = 0; i < 8; ++i) a3[i] = 0.f;
            {
                const uint32_t rb_ = smb + FB_W3H * 2 + lrow * 48 + lcol;
                #pragma unroll
                for (int kk = 0; kk < 4; ++kk) {
                    uint32_t h0, h1, h2, h3, l0, l1, l2, l3;
                    ldmx4(rb_ + kk * 16 * 48, h0, h1, h2, h3);
                    ldmx4(rb_ + kk * 16 * 48 + 3072, l0, l1, l2, l3);
                    mma3(a3 + 0, fh + kk * 4, fl + kk * 4, h0, h1, l0, l1);
                    mma3(a3 + 4, fh + kk * 4, fl + kk * 4, h2, h3, l2, l3);
                }
            }
            float dxv[8];
            dxv[0] = a3[0] + C[192 + d0c];  dxv[1] = a3[1] + C[192 + d0c + 1];
            dxv[2] = a3[2] + C[192 + d0c];  dxv[3] = a3[3] + C[192 + d0c + 1];
            dxv[4] = a3[4] + C[192 + d1c];  dxv[5] = a3[5] + C[192 + d1c + 1];
            dxv[6] = a3[6] + C[192 + d1c];  dxv[7] = a3[7] + C[192 + d1c + 1];

            float dvA = dxv[0] * dxv[0] + dxv[1] * dxv[1] + dxv[4] * dxv[4] + dxv[5] * dxv[5];
            float dvB = dxv[2] * dxv[2] + dxv[3] * dxv[3] + dxv[6] * dxv[6] + dxv[7] * dxv[7];
            dvA += __shfl_xor_sync(0xffffffffu, dvA, 1);
            dvA += __shfl_xor_sync(0xffffffffu, dvA, 2);
            dvB += __shfl_xor_sync(0xffffffffu, dvB, 1);
            dvB += __shfl_xor_sync(0xffffffffu, dvB, 2);

            #pragma unroll
            for (int i = 0; i < 8; ++i) { ksx[i] += wq * dxv[i]; kxp[i] = dxv[i]; }
            ksvA += wq * dvA;
            ksvB += wq * dvB;
        }

        const float scl = hstep * (1.f / 6.f);
        #pragma unroll
        for (int i = 0; i < 8; ++i) xs[i] += scl * ksx[i];
        vA += scl * 0.5f * ksvA;
        vB += scl * 0.5f * ksvB;

        float* os = out + (step + 1) * BATCH * Dd;
        *(float2*)(os + rowA * 16 + d0c) = make_float2(xs[0], xs[1]);
        *(float2*)(os + rowB * 16 + d0c) = make_float2(xs[2], xs[3]);
        *(float2*)(os + rowA * 16 + d1c) = make_float2(xs[4], xs[5]);
        *(float2*)(os + rowB * 16 + d1c) = make_float2(xs[6], xs[7]);
    }

    if (tig == 0) {
        const int base = 3 * BATCH * Dd;
        out[base + BATCH + rowA] = fabsf(vA);
        out[base + BATCH + rowB] = fabsf(vB);
        out[base + 2 * BATCH + rowA] = 0.f;
        out[base + 2 * BATCH + rowB] = 0.f;
    }
}

// ================= tangent kernel (fp16 single-pass mma) =================
// smem floats: [B fp16 planes 4608][Tf 2176][d 12288]
#define TS_TF 4608
#define TS_DV (TS_TF + TF_FLOATS)
#define TS_FLOATS (TS_DV + 64 * 192)
#define TS_BYTES (TS_FLOATS * 4)

__global__ __launch_bounds__(256, 2)
void tangent_kernel()
{
    extern __shared__ float sm[];
    const int tid = threadIdx.x;
    const int lane = tid & 31;
    const int wid = tid >> 5;

    const int e = blockIdx.x >> 9;
    const int rg = blockIdx.x & 511;
    const int row0 = rg * 64;
    const int tmap[8] = {0, 1, 1, 2, 2, 3, 3, 4};
    const int tt = tmap[e];

    {
        const uint4* bsrc = (const uint4*)(g_Thf + (size_t)tt * 2 * BP_ELEMS);
        uint4* bdst = (uint4*)sm;
        #pragma unroll 1
        for (int i = tid; i < (2 * BP_ELEMS * 2) / 16; i += 256) bdst[i] = __ldg(bsrc + i);
        const uint4* fsrc = (const uint4*)(g_Tf + tt * TF_FLOATS);
        uint4* fdst = (uint4*)(sm + TS_TF);
        #pragma unroll 1
        for (int i = tid; i < TF_FLOATS / 4; i += 256) fdst[i] = __ldg(fsrc + i);
        const uint4* dsrc = (const uint4*)(g_d + ((size_t)e * BATCH + row0) * 192);
        uint4* ddst = (uint4*)(sm + TS_DV);
        #pragma unroll 1
        for (int i = tid; i < (64 * 192) / 4; i += 256) ddst[i] = __ldg(dsrc + i);
    }
    __syncthreads();

    const uint32_t smbB = smem_u32(sm);
    const float* M0f = sm + TS_TF;
    const float* M3T = sm + TS_TF + TF_M3T;

    const int g = lane >> 2;
    const int k0 = (lane & 3) * 2;
    const uint32_t lrow = lane & 15, lcol = (lane >> 4) * 16;

    #pragma unroll 1
    for (int rl = 0; rl < 8; ++rl) {
        const int r = wid * 8 + rl;
        const float* d0p = sm + TS_DV + r * 192;
        const float* d1p = d0p + 64;
        const float* d2p = d0p + 128;

        float acc1[32], acc2[32];
        #pragma unroll
        for (int i = 0; i < 32; ++i) { acc1[i] = 0.f; acc2[i] = 0.f; }

        // ---- GEMM1: U2 = (M0f .* d0) @ B1  (fp16 single-pass) ----
        #pragma unroll
        for (int kk = 0; kk < 4; ++kk) {
            const int K = kk * 16;
            const float2 dA = *(const float2*)(d0p + K + k0);
            const float2 dB = *(const float2*)(d0p + K + k0 + 8);
            const float2 mA = *(const float2*)(M0f + g * TF_STRIDE + K + k0);
            const float2 mB = *(const float2*)(M0f + (g + 8) * TF_STRIDE + K + k0);
            const float2 mC = *(const float2*)(M0f + g * TF_STRIDE + K + k0 + 8);
            const float2 mD = *(const float2*)(M0f + (g + 8) * TF_STRIDE + K + k0 + 8);
            uint32_t ah[4];
            ah[0] = f16pk(mA.x * dA.x, mA.y * dA.y);
            ah[1] = f16pk(mB.x * dA.x, mB.y * dA.y);
            ah[2] = f16pk(mC.x * dB.x, mC.y * dB.y);
            ah[3] = f16pk(mD.x * dB.x, mD.y * dB.y);
            const uint32_t rowaddr = smbB + (K + lrow) * (BP_STRIDE * 2) + lcol;
            #pragma unroll
            for (int p = 0; p < 4; ++p) {
                uint32_t h0, h1, h2, h3;
                ldmx4(rowaddr + p * 32, h0, h1, h2, h3);
                mma16816h(acc1 + (2 * p) * 4, ah, h0, h1);
                mma16816h(acc1 + (2 * p + 1) * 4, ah, h2, h3);
            }
        }

        // ---- GEMM2: W = (M3T .* d2) @ B2 ----
        #pragma unroll
        for (int kk = 0; kk < 4; ++kk) {
            const int K = kk * 16;
            const float2 dA = *(const float2*)(d2p + K + k0);
            const float2 dB = *(const float2*)(d2p + K + k0 + 8);
            const float2 mA = *(const float2*)(M3T + g * TF_STRIDE + K + k0);
            const float2 mB = *(const float2*)(M3T + (g + 8) * TF_STRIDE + K + k0);
            const float2 mC = *(const float2*)(M3T + g * TF_STRIDE + K + k0 + 8);
            const float2 mD = *(const float2*)(M3T + (g + 8) * TF_STRIDE + K + k0 + 8);
            uint32_t ah[4];
            ah[0] = f16pk(mA.x * dA.x, mA.y * dA.y);
            ah[1] = f16pk(mB.x * dA.x, mB.y * dA.y);
            ah[2] = f16pk(mC.x * dB.x, mC.y * dB.y);
            ah[3] = f16pk(mD.x * dB.x, mD.y * dB.y);
            const uint32_t rowaddr = smbB + (K + lrow) * (BP_STRIDE * 2) + lcol + BP_ELEMS * 2;
            #pragma unroll
            for (int p = 0; p < 4; ++p) {
                uint32_t h0, h1, h2, h3;
                ldmx4(rowaddr + p * 32, h0, h1, h2, h3);
                mma16816h(acc2 + (2 * p) * 4, ah, h0, h1);
                mma16816h(acc2 + (2 * p + 1) * 4, ah, h2, h3);
            }
        }

        // ---- dl = sum U2 .* d1 .* W ----
        float dl = 0.f;
        #pragma unroll
        for (int nt = 0; nt < 8; ++nt) {
            const float2 dp = *(const float2*)(d1p + nt * 8 + k0);
            dl = fmaf(acc1[nt * 4 + 0] * dp.x, acc2[nt * 4 + 0], dl);
            dl = fmaf(acc1[nt * 4 + 1] * dp.y, acc2[nt * 4 + 1], dl);
            dl = fmaf(acc1[nt * 4 + 2] * dp.x, acc2[nt * 4 + 2], dl);
            dl = fmaf(acc1[nt * 4 + 3] * dp.y, acc2[nt * 4 + 3], dl);
        }
        #pragma unroll
        for (int m = 1; m <= 16; m <<= 1)
            dl += __shfl_xor_sync(0xffffffffu, dl, m);
        if (lane == 0)
            g_dl[e * BATCH + row0 + r] = dl;
    }
}

// ================= combine kernel =================
__global__ void combine_kernel(const float* __restrict__ ts, float* __restrict__ out)
{
    const int r = blockIdx.x * 256 + threadIdx.x;
    const float h0 = ts[1] - ts[0], h1 = ts[2] - ts[1];
    const float* dl = g_dl;
    float l = (h0 * (1.f / 6.f)) * (dl[r] + 2.f * dl[BATCH + r] + 2.f * dl[2 * BATCH + r] + dl[3 * BATCH + r])
            + (h1 * (1.f / 6.f)) * (dl[4 * BATCH + r] + 2.f * dl[5 * BATCH + r] + 2.f * dl[6 * BATCH + r] + dl[7 * BATCH + r]);
    out[3 * BATCH * Dd + r] = l;
}

extern "C" void kernel_launch(void* const* d_in, const int* in_sizes, int n_in,
                              void* d_out, int out_size) {
    const float* ts  = (const float*)d_in[0];
    const float* x0  = (const float*)d_in[1];
    const float* W0  = (const float*)d_in[2];
    const float* b0  = (const float*)d_in[3];
    const float* g0  = (const float*)d_in[4];
    const float* gb0 = (const float*)d_in[5];
    const float* hb0 = (const float*)d_in[6];
    const float* W1  = (const float*)d_in[7];
    const float* b1  = (const float*)d_in[8];
    const float* g1  = (const float*)d_in[9];
    const float* gb1 = (const float*)d_in[10];
    const float* hb1 = (const float*)d_in[11];
    const float* W2  = (const float*)d_in[12];
    const float* b2  = (const float*)d_in[13];
    const float* g2  = (const float*)d_in[14];
    const float* gb2 = (const float*)d_in[15];
    const float* hb2 = (const float*)d_in[16];
    const float* W3  = (const float*)d_in[17];
    const float* b3  = (const float*)d_in[18];
    const float* g3  = (const float*)d_in[19];
    const float* gb3 = (const float*)d_in[20];
    const float* hb3 = (const float*)d_in[21];
    float* out = (float*)d_out;

    build_kernel<<<NT, 256>>>(ts,
        W0, b0, g0, gb0, hb0,
        W1, b1, g1, gb1, hb1,
        W2, b2, g2, gb2, hb2,
        W3, b3, g3, gb3, hb3);

    cudaFuncSetAttribute(forward_kernel, cudaFuncAttributeMaxDynamicSharedMemorySize, FWD_SMEM);
    forward_kernel<<<BATCH / 64, 128, FWD_SMEM>>>(ts, x0, out);

    cudaFuncSetAttribute(tangent_kernel, cudaFuncAttributeMaxDynamicSharedMemorySize, TS_BYTES);
    tangent_kernel<<<8 * 512, 256, TS_BYTES>>>();

    combine_kernel<<<BATCH / 256, 256>>>(ts, out);
}

// round 12
// speedup vs baseline: 1.6137x; 1.2999x over previous
#include <cuda_runtime.h>
#include <cuda_bf16.h>
#include <cuda_fp16.h>
#include <cstdint>

#define Dd 16
#define BATCH 32768

typedef unsigned long long ull;

#define NT 5   // distinct t values

// -------- tangent-kernel constants --------
#define TF_STRIDE 68
#define TF_M3T    (16 * TF_STRIDE)
#define TF_FLOATS (2 * 16 * TF_STRIDE)
#define BP_STRIDE 72
#define BP_ELEMS  (64 * BP_STRIDE)

// -------- forward-kernel bf16 weight planes (per t), element offsets --------
#define FB_W0H 0
#define FB_W0L 1152
#define FB_W1H 2304
#define FB_W1L 6912
#define FB_W2H 11520
#define FB_W2L 16128
#define FB_W3H 20736
#define FB_W3L 22272
#define FB_BF  23808
#define FB_BYTES_BF (FB_BF * 2)
#define FB_CF  208
#define STG_STRIDE 68
#define STG_WARP   (16 * STG_STRIDE)
#define FNWARP 8
#define FNT    (FNWARP * 32)
#define FROWS  (FNWARP * 16)
#define FWD_SMEM (FB_BYTES_BF + FB_CF * 4 + FNWARP * STG_WARP * 4)

__device__ __align__(16) float g_Tf[NT * TF_FLOATS];
__device__ __align__(16) __half g_Thf[NT * 2 * BP_ELEMS];   // fp16 B planes: B1, B2
__device__ __align__(16) __nv_bfloat16 g_FWb[NT * FB_BF];
__device__ __align__(16) float g_FWc[NT * FB_CF];
__device__ float g_d[8ull * BATCH * 192];
__device__ float g_dl[8 * BATCH];

__device__ __forceinline__ float sigm(float x) {
    return __fdividef(1.f, 1.f + __expf(-x));
}
__device__ __forceinline__ float tanh_f(float x) {
    x = fminf(fmaxf(x, -15.f), 15.f);
    float e = __expf(-2.f * x);
    return __fdividef(1.f - e, 1.f + e);
}
__device__ __forceinline__ uint32_t smem_u32(const void* p) {
    uint32_t a;
    asm("{ .reg .u64 t; cvta.to.shared.u64 t, %1; cvt.u32.u64 %0, t; }" : "=r"(a) : "l"(p));
    return a;
}
__device__ __forceinline__ uint32_t bf2_split(float v0, float v1, uint32_t& lo) {
    uint32_t h;
    asm("cvt.rn.bf16x2.f32 %0, %1, %2;" : "=r"(h) : "f"(v1), "f"(v0));
    float r0 = v0 - __uint_as_float(h << 16);
    float r1 = v1 - __uint_as_float(h & 0xFFFF0000u);
    asm("cvt.rn.bf16x2.f32 %0, %1, %2;" : "=r"(lo) : "f"(r1), "f"(r0));
    return h;
}
__device__ __forceinline__ uint32_t f16pk(float v0, float v1) {
    uint32_t r;
    asm("cvt.rn.f16x2.f32 %0, %1, %2;" : "=r"(r) : "f"(v1), "f"(v0));
    return r;
}
__device__ __forceinline__ void ldmx4(uint32_t addr, uint32_t& r0, uint32_t& r1,
                                      uint32_t& r2, uint32_t& r3) {
    asm volatile("ldmatrix.sync.aligned.m8n8.x4.trans.shared.b16 {%0,%1,%2,%3}, [%4];"
                 : "=r"(r0), "=r"(r1), "=r"(r2), "=r"(r3) : "r"(addr));
}
__device__ __forceinline__ void mma16816(float* c, const uint32_t* a, uint32_t b0, uint32_t b1) {
    asm("mma.sync.aligned.m16n8k16.row.col.f32.bf16.bf16.f32 "
        "{%0,%1,%2,%3}, {%4,%5,%6,%7}, {%8,%9}, {%0,%1,%2,%3};"
        : "+f"(c[0]), "+f"(c[1]), "+f"(c[2]), "+f"(c[3])
        : "r"(a[0]), "r"(a[1]), "r"(a[2]), "r"(a[3]), "r"(b0), "r"(b1));
}
__device__ __forceinline__ void mma16816h(float* c, const uint32_t* a, uint32_t b0, uint32_t b1) {
    asm("mma.sync.aligned.m16n8k16.row.col.f32.f16.f16.f32 "
        "{%0,%1,%2,%3}, {%4,%5,%6,%7}, {%8,%9}, {%0,%1,%2,%3};"
        : "+f"(c[0]), "+f"(c[1]), "+f"(c[2]), "+f"(c[3])
        : "r"(a[0]), "r"(a[1]), "r"(a[2]), "r"(a[3]), "r"(b0), "r"(b1));
}
__device__ __forceinline__ void mma3(float* c, const uint32_t* ah, const uint32_t* al,
                                     uint32_t bh0, uint32_t bh1, uint32_t bl0, uint32_t bl1) {
    mma16816(c, ah, bh0, bh1);
    mma16816(c, al, bh0, bh1);
    mma16816(c, ah, bl0, bl1);
}

// ---------------- build kernel ----------------
__global__ void build_kernel(const float* __restrict__ ts,
    const float* __restrict__ W0, const float* __restrict__ b0, const float* __restrict__ g0, const float* __restrict__ gb0, const float* __restrict__ hb0,
    const float* __restrict__ W1, const float* __restrict__ b1, const float* __restrict__ g1, const float* __restrict__ gb1, const float* __restrict__ hb1,
    const float* __restrict__ W2, const float* __restrict__ b2, const float* __restrict__ g2, const float* __restrict__ gb2, const float* __restrict__ hb2,
    const float* __restrict__ W3, const float* __restrict__ b3, const float* __restrict__ g3, const float* __restrict__ gb3, const float* __restrict__ hb3)
{
    const int tt = blockIdx.x;
    const float ts0 = ts[0], ts1 = ts[1], ts2 = ts[2];
    float t;
    if (tt == 0) t = ts0;
    else if (tt == 1) t = ts0 + 0.5f * (ts1 - ts0);
    else if (tt == 2) t = ts1;
    else if (tt == 3) t = ts1 + 0.5f * (ts2 - ts1);
    else t = ts2;

    float* tf = g_Tf + tt * TF_FLOATS;
    __half* hp = g_Thf + (size_t)tt * 2 * BP_ELEMS;
    __nv_bfloat16* fw = g_FWb + (size_t)tt * FB_BF;
    float* fc = g_FWc + tt * FB_CF;
    const int tid = threadIdx.x;

    for (int i = tid; i < 1024; i += blockDim.x) {
        int j = i >> 6, c = i & 63;
        float v = W0[i] * sigm(t * g0[c] + gb0[c]);
        tf[j * TF_STRIDE + c] = v;
        __nv_bfloat16 h = __float2bfloat16_rn(v);
        __nv_bfloat16 l = __float2bfloat16_rn(v - __bfloat162float(h));
        fw[FB_W0H + j * 72 + c] = h;
        fw[FB_W0L + j * 72 + c] = l;
    }
    for (int i = tid; i < 4096; i += blockDim.x) {
        int a = i >> 6, b = i & 63;
        float v = W1[i] * sigm(t * g1[b] + gb1[b]);
        __nv_bfloat16 h = __float2bfloat16_rn(v);
        __nv_bfloat16 l = __float2bfloat16_rn(v - __bfloat162float(h));
        fw[FB_W1H + a * 72 + b] = h;
        fw[FB_W1L + a * 72 + b] = l;
        hp[0 * BP_ELEMS + a * BP_STRIDE + b] = __float2half_rn(v);
    }
    for (int i = tid; i < 4096; i += blockDim.x) {
        int b = i >> 6, c = i & 63;
        float v = W2[i] * sigm(t * g2[c] + gb2[c]);
        __nv_bfloat16 h = __float2bfloat16_rn(v);
        __nv_bfloat16 l = __float2bfloat16_rn(v - __bfloat162float(h));
        fw[FB_W2H + b * 72 + c] = h;
        fw[FB_W2L + b * 72 + c] = l;
        hp[1 * BP_ELEMS + c * BP_STRIDE + b] = __float2half_rn(v);
    }
    for (int i = tid; i < 1024; i += blockDim.x) {
        int j = i >> 4, e = i & 15;
        float v = W3[i] * sigm(t * g3[e] + gb3[e]);
        tf[TF_M3T + e * TF_STRIDE + j] = v;
        __nv_bfloat16 h = __float2bfloat16_rn(v);
        __nv_bfloat16 l = __float2bfloat16_rn(v - __bfloat162float(h));
        fw[FB_W3H + j * 24 + e] = h;
        fw[FB_W3L + j * 24 + e] = l;
    }
    if (tid < 64) {
        float s0 = sigm(t * g0[tid] + gb0[tid]);
        float s1 = sigm(t * g1[tid] + gb1[tid]);
        float s2 = sigm(t * g2[tid] + gb2[tid]);
        fc[0 + tid]   = b0[tid] * s0 + t * hb0[tid];
        fc[64 + tid]  = b1[tid] * s1 + t * hb1[tid];
        fc[128 + tid] = b2[tid] * s2 + t * hb2[tid];
        if (tid < 16) {
            float s3 = sigm(t * g3[tid] + gb3[tid]);
            fc[192 + tid] = b3[tid] * s3 + t * hb3[tid];
        }
    }
}

// ================= forward kernel (256 thr, 128 rows/CTA, occ 2, 1 wave) =================
__device__ __forceinline__ void fwd_epi(const float* acc, const float* Cv,
                                        float* stg, int g, int tig,
                                        uint32_t* fh, uint32_t* fl)
{
    #pragma unroll
    for (int nt = 0; nt < 8; ++nt) {
        const int col = nt * 8 + 2 * tig;
        const float b0 = Cv[col], b1 = Cv[col + 1];
        const float h0 = tanh_f(acc[nt * 4 + 0] + b0);
        const float h1 = tanh_f(acc[nt * 4 + 1] + b1);
        const float h2 = tanh_f(acc[nt * 4 + 2] + b0);
        const float h3 = tanh_f(acc[nt * 4 + 3] + b1);
        *(float2*)(stg + g * STG_STRIDE + col)       = make_float2(1.f - h0 * h0, 1.f - h1 * h1);
        *(float2*)(stg + (g + 8) * STG_STRIDE + col) = make_float2(1.f - h2 * h2, 1.f - h3 * h3);
        const int kk = nt >> 1, hf = nt & 1;
        fh[kk * 4 + hf * 2 + 0] = bf2_split(h0, h1, fl[kk * 4 + hf * 2 + 0]);
        fh[kk * 4 + hf * 2 + 1] = bf2_split(h2, h3, fl[kk * 4 + hf * 2 + 1]);
    }
}

__device__ __forceinline__ void stage_flush(const float* stg, float* dst, int lane)
{
    #pragma unroll
    for (int k = 0; k < 8; ++k) {
        const int idx4 = lane + k * 32;
        const int row = idx4 >> 4, c4 = idx4 & 15;
        *(float4*)(dst + row * 192 + c4 * 4) = *(const float4*)(stg + row * STG_STRIDE + c4 * 4);
    }
}

__global__ __launch_bounds__(FNT, 2)
void forward_kernel(const float* __restrict__ ts, const float* __restrict__ x0,
                    float* __restrict__ out)
{
    extern __shared__ char smc[];
    float* C = (float*)(smc + FB_BYTES_BF);
    float* stage = (float*)(smc + FB_BYTES_BF + FB_CF * 4);

    const int tid  = threadIdx.x;
    const int lane = tid & 31;
    const int wid  = tid >> 5;
    const int g = lane >> 2, tig = lane & 3;
    const int d0c = 2 * tig, d1c = 8 + 2 * tig;

    float* stg = stage + wid * STG_WARP;
    const int rowbase = blockIdx.x * FROWS + wid * 16;
    const int rowA = rowbase + g;
    const int rowB = rowA + 8;

    const uint32_t smb = smem_u32(smc);
    const uint32_t lrow = lane & 15, lcol = (lane >> 4) * 16;

    const float ts0 = ts[0], ts1 = ts[1], ts2 = ts[2];
    const float tst[3] = {ts0, ts1, ts2};

    float xs[8];
    {
        float2 p0 = *(const float2*)(x0 + rowA * 16 + d0c);
        float2 p1 = *(const float2*)(x0 + rowB * 16 + d0c);
        float2 p2 = *(const float2*)(x0 + rowA * 16 + d1c);
        float2 p3 = *(const float2*)(x0 + rowB * 16 + d1c);
        xs[0] = p0.x; xs[1] = p0.y; xs[2] = p1.x; xs[3] = p1.y;
        xs[4] = p2.x; xs[5] = p2.y; xs[6] = p3.x; xs[7] = p3.y;
        *(float2*)(out + rowA * 16 + d0c) = p0;
        *(float2*)(out + rowB * 16 + d0c) = p1;
        *(float2*)(out + rowA * 16 + d1c) = p2;
        *(float2*)(out + rowB * 16 + d1c) = p3;
    }
    float vA = 0.f, vB = 0.f;
    int ptt = -1;

    #pragma unroll 1
    for (int step = 0; step < 2; ++step) {
        const float tA = tst[step];
        const float hstep = tst[step + 1] - tA;
        float ksx[8], kxp[8];
        #pragma unroll
        for (int i = 0; i < 8; ++i) { ksx[i] = 0.f; kxp[i] = 0.f; }
        float ksvA = 0.f, ksvB = 0.f;

        #pragma unroll 1
        for (int stage_i = 0; stage_i < 4; ++stage_i) {
            const int tt = step * 2 + ((stage_i == 0) ? 0 : ((stage_i == 3) ? 2 : 1));
            if (tt != ptt) {
                __syncthreads();
                const uint4* src = (const uint4*)(g_FWb + (size_t)tt * FB_BF);
                uint4* dst = (uint4*)smc;
                #pragma unroll 4
                for (int i = tid; i < FB_BYTES_BF / 16; i += FNT) dst[i] = __ldg(src + i);
                const uint4* cs = (const uint4*)(g_FWc + tt * FB_CF);
                uint4* cd = (uint4*)(smc + FB_BYTES_BF);
                if (tid < FB_CF / 4) cd[tid] = __ldg(cs + tid);
                __syncthreads();
                ptt = tt;
            }
            const int e = step * 4 + stage_i;
            const float coef = (stage_i == 0) ? 0.f : ((stage_i == 3) ? hstep : 0.5f * hstep);
            const float wq = (stage_i == 1 || stage_i == 2) ? 2.f : 1.f;

            float* gdw = g_d + ((size_t)e * BATCH + rowbase) * 192;

            uint32_t fh[16], fl[16];
            {
                float xe[8];
                #pragma unroll
                for (int i = 0; i < 8; ++i) xe[i] = xs[i] + coef * kxp[i];
                fh[0] = bf2_split(xe[0], xe[1], fl[0]);
                fh[1] = bf2_split(xe[2], xe[3], fl[1]);
                fh[2] = bf2_split(xe[4], xe[5], fl[2]);
                fh[3] = bf2_split(xe[6], xe[7], fl[3]);
            }
            float acc[32];

            // ---- L0 ----
            #pragma unroll
            for (int i = 0; i < 32; ++i) acc[i] = 0.f;
            {
                const uint32_t rb_ = smb + FB_W0H * 2 + lrow * 144 + lcol;
                #pragma unroll
                for (int p = 0; p < 4; ++p) {
                    uint32_t h0, h1, h2, h3, l0, l1, l2, l3;
                    ldmx4(rb_ + p * 32, h0, h1, h2, h3);
                    ldmx4(rb_ + p * 32 + 2304, l0, l1, l2, l3);
                    mma3(acc + (2 * p) * 4, fh, fl, h0, h1, l0, l1);
                    mma3(acc + (2 * p + 1) * 4, fh, fl, h2, h3, l2, l3);
                }
            }
            fwd_epi(acc, C + 0, stg, g, tig, fh, fl);
            __syncwarp();
            stage_flush(stg, gdw + 0, lane);
            __syncwarp();

            // ---- L1 ----
            #pragma unroll
            for (int i = 0; i < 32; ++i) acc[i] = 0.f;
            {
                const uint32_t rb_ = smb + FB_W1H * 2 + lrow * 144 + lcol;
                #pragma unroll
                for (int kk = 0; kk < 4; ++kk) {
                    const uint32_t rk = rb_ + kk * 16 * 144;
                    #pragma unroll
                    for (int p = 0; p < 4; ++p) {
                        uint32_t h0, h1, h2, h3, l0, l1, l2, l3;
                        ldmx4(rk + p * 32, h0, h1, h2, h3);
                        ldmx4(rk + p * 32 + 9216, l0, l1, l2, l3);
                        mma3(acc + (2 * p) * 4, fh + kk * 4, fl + kk * 4, h0, h1, l0, l1);
                        mma3(acc + (2 * p + 1) * 4, fh + kk * 4, fl + kk * 4, h2, h3, l2, l3);
                    }
                }
            }
            fwd_epi(acc, C + 64, stg, g, tig, fh, fl);
            __syncwarp();
            stage_flush(stg, gdw + 64, lane);
            __syncwarp();

            // ---- L2 ----
            #pragma unroll
            for (int i = 0; i < 32; ++i) acc[i] = 0.f;
            {
                const uint32_t rb_ = smb + FB_W2H * 2 + lrow * 144 + lcol;
                #pragma unroll
                for (int kk = 0; kk < 4; ++kk) {
                    const uint32_t rk = rb_ + kk * 16 * 144;
                    #pragma unroll
                    for (int p = 0; p < 4; ++p) {
                        uint32_t h0, h1, h2, h3, l0, l1, l2, l3;
                        ldmx4(rk + p * 32, h0, h1, h2, h3);
                        ldmx4(rk + p * 32 + 9216, l0, l1, l2, l3);
                        mma3(acc + (2 * p) * 4, fh + kk * 4, fl + kk * 4, h0, h1, l0, l1);
                        mma3(acc + (2 * p + 1) * 4, fh + kk * 4, fl + kk * 4, h2, h3, l2, l3);
                    }
                }
            }
            fwd_epi(acc, C + 128, stg, g, tig, fh, fl);
            __syncwarp();
            stage_flush(stg, gdw + 128, lane);
            __syncwarp();

            // ---- L3 ----
            float a3[8];
            #pragma unroll
            for (int i = 0; i < 8; ++i) a3[i] = 0.f;
            {
                const uint32_t rb_ = smb + FB_W3H * 2 + lrow * 48 + lcol;
                #pragma unroll
                for (int kk = 0; kk < 4; ++kk) {
                    uint32_t h0, h1, h2, h3, l0, l1, l2, l3;
                    ldmx4(rb_ + kk * 16 * 48, h0, h1, h2, h3);
                    ldmx4(rb_ + kk * 16 * 48 + 3072, l0, l1, l2, l3);
                    mma3(a3 + 0, fh + kk * 4, fl + kk * 4, h0, h1, l0, l1);
                    mma3(a3 + 4, fh + kk * 4, fl + kk * 4, h2, h3, l2, l3);
                }
            }
            float dxv[8];
            dxv[0] = a3[0] + C[192 + d0c];  dxv[1] = a3[1] + C[192 + d0c + 1];
            dxv[2] = a3[2] + C[192 + d0c];  dxv[3] = a3[3] + C[192 + d0c + 1];
            dxv[4] = a3[4] + C[192 + d1c];  dxv[5] = a3[5] + C[192 + d1c + 1];
            dxv[6] = a3[6] + C[192 + d1c];  dxv[7] = a3[7] + C[192 + d1c + 1];

            float dvA = dxv[0] * dxv[0] + dxv[1] * dxv[1] + dxv[4] * dxv[4] + dxv[5] * dxv[5];
            float dvB = dxv[2] * dxv[2] + dxv[3] * dxv[3] + dxv[6] * dxv[6] + dxv[7] * dxv[7];
            dvA += __shfl_xor_sync(0xffffffffu, dvA, 1);
            dvA += __shfl_xor_sync(0xffffffffu, dvA, 2);
            dvB += __shfl_xor_sync(0xffffffffu, dvB, 1);
            dvB += __shfl_xor_sync(0xffffffffu, dvB, 2);

            #pragma unroll
            for (int i = 0; i < 8; ++i) { ksx[i] += wq * dxv[i]; kxp[i] = dxv[i]; }
            ksvA += wq * dvA;
            ksvB += wq * dvB;
        }

        const float scl = hstep * (1.f / 6.f);
        #pragma unroll
        for (int i = 0; i < 8; ++i) xs[i] += scl * ksx[i];
        vA += scl * 0.5f * ksvA;
        vB += scl * 0.5f * ksvB;

        float* os = out + (step + 1) * BATCH * Dd;
        *(float2*)(os + rowA * 16 + d0c) = make_float2(xs[0], xs[1]);
        *(float2*)(os + rowB * 16 + d0c) = make_float2(xs[2], xs[3]);
        *(float2*)(os + rowA * 16 + d1c) = make_float2(xs[4], xs[5]);
        *(float2*)(os + rowB * 16 + d1c) = make_float2(xs[6], xs[7]);
    }

    if (tig == 0) {
        const int base = 3 * BATCH * Dd;
        out[base + BATCH + rowA] = fabsf(vA);
        out[base + BATCH + rowB] = fabsf(vB);
        out[base + 2 * BATCH + rowA] = 0.f;
        out[base + 2 * BATCH + rowB] = 0.f;
    }
}

// ================= tangent kernel (fp16 single-pass mma; identical arithmetic) =================
#define TS_TF 4608
#define TS_DV (TS_TF + TF_FLOATS)
#define TS_FLOATS (TS_DV + 64 * 192)
#define TS_BYTES (TS_FLOATS * 4)

__global__ __launch_bounds__(256, 2)
void tangent_kernel()
{
    extern __shared__ float sm[];
    const int tid = threadIdx.x;
    const int lane = tid & 31;
    const int wid = tid >> 5;

    const int e = blockIdx.x >> 9;
    const int rg = blockIdx.x & 511;
    const int row0 = rg * 64;
    const int tmap[8] = {0, 1, 1, 2, 2, 3, 3, 4};
    const int tt = tmap[e];

    {
        const uint4* bsrc = (const uint4*)(g_Thf + (size_t)tt * 2 * BP_ELEMS);
        uint4* bdst = (uint4*)sm;
        #pragma unroll 4
        for (int i = tid; i < (2 * BP_ELEMS * 2) / 16; i += 256) bdst[i] = __ldg(bsrc + i);
        const uint4* fsrc = (const uint4*)(g_Tf + tt * TF_FLOATS);
        uint4* fdst = (uint4*)(sm + TS_TF);
        #pragma unroll 2
        for (int i = tid; i < TF_FLOATS / 4; i += 256) fdst[i] = __ldg(fsrc + i);
        const uint4* dsrc = (const uint4*)(g_d + ((size_t)e * BATCH + row0) * 192);
        uint4* ddst = (uint4*)(sm + TS_DV);
        #pragma unroll 4
        for (int i = tid; i < (64 * 192) / 4; i += 256) ddst[i] = __ldg(dsrc + i);
    }
    __syncthreads();

    const uint32_t smbB = smem_u32(sm);
    const float* M0f = sm + TS_TF;
    const float* M3T = sm + TS_TF + TF_M3T;

    const int g = lane >> 2;
    const int k0 = (lane & 3) * 2;
    const uint32_t lrow = lane & 15, lcol = (lane >> 4) * 16;

    #pragma unroll 1
    for (int rl = 0; rl < 8; ++rl) {
        const int r = wid * 8 + rl;
        const float* d0p = sm + TS_DV + r * 192;
        const float* d1p = d0p + 64;
        const float* d2p = d0p + 128;

        float acc1[32], acc2[32];
        #pragma unroll
        for (int i = 0; i < 32; ++i) { acc1[i] = 0.f; acc2[i] = 0.f; }

        // ---- GEMM1: U2 = (M0f .* d0) @ B1 ----
        #pragma unroll
        for (int kk = 0; kk < 4; ++kk) {
            const int K = kk * 16;
            const float2 dA = *(const float2*)(d0p + K + k0);
            const float2 dB = *(const float2*)(d0p + K + k0 + 8);
            const float2 mA = *(const float2*)(M0f + g * TF_STRIDE + K + k0);
            const float2 mB = *(const float2*)(M0f + (g + 8) * TF_STRIDE + K + k0);
            const float2 mC = *(const float2*)(M0f + g * TF_STRIDE + K + k0 + 8);
            const float2 mD = *(const float2*)(M0f + (g + 8) * TF_STRIDE + K + k0 + 8);
            uint32_t ah[4];
            ah[0] = f16pk(mA.x * dA.x, mA.y * dA.y);
            ah[1] = f16pk(mB.x * dA.x, mB.y * dA.y);
            ah[2] = f16pk(mC.x * dB.x, mC.y * dB.y);
            ah[3] = f16pk(mD.x * dB.x, mD.y * dB.y);
            const uint32_t rowaddr = smbB + (K + lrow) * (BP_STRIDE * 2) + lcol;
            #pragma unroll
            for (int p = 0; p < 4; ++p) {
                uint32_t h0, h1, h2, h3;
                ldmx4(rowaddr + p * 32, h0, h1, h2, h3);
                mma16816h(acc1 + (2 * p) * 4, ah, h0, h1);
                mma16816h(acc1 + (2 * p + 1) * 4, ah, h2, h3);
            }
        }

        // ---- GEMM2: W = (M3T .* d2) @ B2 ----
        #pragma unroll
        for (int kk = 0; kk < 4; ++kk) {
            const int K = kk * 16;
            const float2 dA = *(const float2*)(d2p + K + k0);
            const float2 dB = *(const float2*)(d2p + K + k0 + 8);
            const float2 mA = *(const float2*)(M3T + g * TF_STRIDE + K + k0);
            const float2 mB = *(const float2*)(M3T + (g + 8) * TF_STRIDE + K + k0);
            const float2 mC = *(const float2*)(M3T + g * TF_STRIDE + K + k0 + 8);
            const float2 mD = *(const float2*)(M3T + (g + 8) * TF_STRIDE + K + k0 + 8);
            uint32_t ah[4];
            ah[0] = f16pk(mA.x * dA.x, mA.y * dA.y);
            ah[1] = f16pk(mB.x * dA.x, mB.y * dA.y);
            ah[2] = f16pk(mC.x * dB.x, mC.y * dB.y);
            ah[3] = f16pk(mD.x * dB.x, mD.y * dB.y);
            const uint32_t rowaddr = smbB + (K + lrow) * (BP_STRIDE * 2) + lcol + BP_ELEMS * 2;
            #pragma unroll
            for (int p = 0; p < 4; ++p) {
                uint32_t h0, h1, h2, h3;
                ldmx4(rowaddr + p * 32, h0, h1, h2, h3);
                mma16816h(acc2 + (2 * p) * 4, ah, h0, h1);
                mma16816h(acc2 + (2 * p + 1) * 4, ah, h2, h3);
            }
        }

        // ---- dl = sum U2 .* d1 .* W ----
        float dl = 0.f;
        #pragma unroll
        for (int nt = 0; nt < 8; ++nt) {
            const float2 dp = *(const float2*)(d1p + nt * 8 + k0);
            dl = fmaf(acc1[nt * 4 + 0] * dp.x, acc2[nt * 4 + 0], dl);
            dl = fmaf(acc1[nt * 4 + 1] * dp.y, acc2[nt * 4 + 1], dl);
            dl = fmaf(acc1[nt * 4 + 2] * dp.x, acc2[nt * 4 + 2], dl);
            dl = fmaf(acc1[nt * 4 + 3] * dp.y, acc2[nt * 4 + 3], dl);
        }
        #pragma unroll
        for (int m = 1; m <= 16; m <<= 1)
            dl += __shfl_xor_sync(0xffffffffu, dl, m);
        if (lane == 0)
            g_dl[e * BATCH + row0 + r] = dl;
    }
}

// ================= combine kernel =================
__global__ void combine_kernel(const float* __restrict__ ts, float* __restrict__ out)
{
    const int r = blockIdx.x * 256 + threadIdx.x;
    const float h0 = ts[1] - ts[0], h1 = ts[2] - ts[1];
    const float* dl = g_dl;
    float l = (h0 * (1.f / 6.f)) * (dl[r] + 2.f * dl[BATCH + r] + 2.f * dl[2 * BATCH + r] + dl[3 * BATCH + r])
            + (h1 * (1.f / 6.f)) * (dl[4 * BATCH + r] + 2.f * dl[5 * BATCH + r] + 2.f * dl[6 * BATCH + r] + dl[7 * BATCH + r]);
    out[3 * BATCH * Dd + r] = l;
}

extern "C" void kernel_launch(void* const* d_in, const int* in_sizes, int n_in,
                              void* d_out, int out_size) {
    const float* ts  = (const float*)d_in[0];
    const float* x0  = (const float*)d_in[1];
    const float* W0  = (const float*)d_in[2];
    const float* b0  = (const float*)d_in[3];
    const float* g0  = (const float*)d_in[4];
    const float* gb0 = (const float*)d_in[5];
    const float* hb0 = (const float*)d_in[6];
    const float* W1  = (const float*)d_in[7];
    const float* b1  = (const float*)d_in[8];
    const float* g1  = (const float*)d_in[9];
    const float* gb1 = (const float*)d_in[10];
    const float* hb1 = (const float*)d_in[11];
    const float* W2  = (const float*)d_in[12];
    const float* b2  = (const float*)d_in[13];
    const float* g2  = (const float*)d_in[14];
    const float* gb2 = (const float*)d_in[15];
    const float* hb2 = (const float*)d_in[16];
    const float* W3  = (const float*)d_in[17];
    const float* b3  = (const float*)d_in[18];
    const float* g3  = (const float*)d_in[19];
    const float* gb3 = (const float*)d_in[20];
    const float* hb3 = (const float*)d_in[21];
    float* out = (float*)d_out;

    build_kernel<<<NT, 256>>>(ts,
        W0, b0, g0, gb0, hb0,
        W1, b1, g1, gb1, hb1,
        W2, b2, g2, gb2, hb2,
        W3, b3, g3, gb3, hb3);

    cudaFuncSetAttribute(forward_kernel, cudaFuncAttributeMaxDynamicSharedMemorySize, FWD_SMEM);
    forward_kernel<<<BATCH / FROWS, FNT, FWD_SMEM>>>(ts, x0, out);

    cudaFuncSetAttribute(tangent_kernel, cudaFuncAttributeMaxDynamicSharedMemorySize, TS_BYTES);
    tangent_kernel<<<8 * 512, 256, TS_BYTES>>>();

    combine_kernel<<<BATCH / 256, 256>>>(ts, out);
}

// round 13
// speedup vs baseline: 1.6169x; 1.0020x over previous
#include <cuda_runtime.h>
#include <cuda_bf16.h>
#include <cuda_fp16.h>
#include <cstdint>

#define Dd 16
#define BATCH 32768

typedef unsigned long long ull;

#define NT 5   // distinct t values

// -------- tangent-kernel constants --------
#define TF_STRIDE 68
#define TF_M3T    (16 * TF_STRIDE)
#define TF_FLOATS (2 * 16 * TF_STRIDE)
#define BP_STRIDE 72
#define BP_ELEMS  (64 * BP_STRIDE)

// -------- forward-kernel bf16 weight planes (per t), element offsets --------
#define FB_W0H 0
#define FB_W0L 1152
#define FB_W1H 2304
#define FB_W1L 6912
#define FB_W2H 11520
#define FB_W2L 16128
#define FB_W3H 20736
#define FB_W3L 22272
#define FB_BF  23808
#define FB_BYTES_BF (FB_BF * 2)
#define FB_CF  208
#define STG_STRIDE 68
#define STG_WARP   (16 * STG_STRIDE)
#define FNWARP 8
#define FNT    (FNWARP * 32)
#define FROWS  (FNWARP * 16)
#define FWD_SMEM (FB_BYTES_BF + FB_CF * 4 + FNWARP * STG_WARP * 4)

__device__ __align__(16) float g_Tf[NT * TF_FLOATS];
__device__ __align__(16) __half g_Thf[NT * 2 * BP_ELEMS];   // fp16 B planes: B1, B2
__device__ __align__(16) __nv_bfloat16 g_FWb[NT * FB_BF];
__device__ __align__(16) float g_FWc[NT * FB_CF];
__device__ float g_d[8ull * BATCH * 192];

__device__ __forceinline__ float sigm(float x) {
    return __fdividef(1.f, 1.f + __expf(-x));
}
__device__ __forceinline__ float tanh_f(float x) {
    x = fminf(fmaxf(x, -15.f), 15.f);
    float e = __expf(-2.f * x);
    return __fdividef(1.f - e, 1.f + e);
}
__device__ __forceinline__ uint32_t smem_u32(const void* p) {
    uint32_t a;
    asm("{ .reg .u64 t; cvta.to.shared.u64 t, %1; cvt.u32.u64 %0, t; }" : "=r"(a) : "l"(p));
    return a;
}
__device__ __forceinline__ uint32_t bf2_split(float v0, float v1, uint32_t& lo) {
    uint32_t h;
    asm("cvt.rn.bf16x2.f32 %0, %1, %2;" : "=r"(h) : "f"(v1), "f"(v0));
    float r0 = v0 - __uint_as_float(h << 16);
    float r1 = v1 - __uint_as_float(h & 0xFFFF0000u);
    asm("cvt.rn.bf16x2.f32 %0, %1, %2;" : "=r"(lo) : "f"(r1), "f"(r0));
    return h;
}
__device__ __forceinline__ uint32_t f16pk(float v0, float v1) {
    uint32_t r;
    asm("cvt.rn.f16x2.f32 %0, %1, %2;" : "=r"(r) : "f"(v1), "f"(v0));
    return r;
}
__device__ __forceinline__ void ldmx4(uint32_t addr, uint32_t& r0, uint32_t& r1,
                                      uint32_t& r2, uint32_t& r3) {
    asm volatile("ldmatrix.sync.aligned.m8n8.x4.trans.shared.b16 {%0,%1,%2,%3}, [%4];"
                 : "=r"(r0), "=r"(r1), "=r"(r2), "=r"(r3) : "r"(addr));
}
__device__ __forceinline__ void mma16816(float* c, const uint32_t* a, uint32_t b0, uint32_t b1) {
    asm("mma.sync.aligned.m16n8k16.row.col.f32.bf16.bf16.f32 "
        "{%0,%1,%2,%3}, {%4,%5,%6,%7}, {%8,%9}, {%0,%1,%2,%3};"
        : "+f"(c[0]), "+f"(c[1]), "+f"(c[2]), "+f"(c[3])
        : "r"(a[0]), "r"(a[1]), "r"(a[2]), "r"(a[3]), "r"(b0), "r"(b1));
}
__device__ __forceinline__ void mma16816h(float* c, const uint32_t* a, uint32_t b0, uint32_t b1) {
    asm("mma.sync.aligned.m16n8k16.row.col.f32.f16.f16.f32 "
        "{%0,%1,%2,%3}, {%4,%5,%6,%7}, {%8,%9}, {%0,%1,%2,%3};"
        : "+f"(c[0]), "+f"(c[1]), "+f"(c[2]), "+f"(c[3])
        : "r"(a[0]), "r"(a[1]), "r"(a[2]), "r"(a[3]), "r"(b0), "r"(b1));
}
__device__ __forceinline__ void mma3(float* c, const uint32_t* ah, const uint32_t* al,
                                     uint32_t bh0, uint32_t bh1, uint32_t bl0, uint32_t bl1) {
    mma16816(c, ah, bh0, bh1);
    mma16816(c, al, bh0, bh1);
    mma16816(c, ah, bl0, bl1);
}

// ---------------- build kernel ----------------
__global__ void build_kernel(const float* __restrict__ ts,
    const float* __restrict__ W0, const float* __restrict__ b0, const float* __restrict__ g0, const float* __restrict__ gb0, const float* __restrict__ hb0,
    const float* __restrict__ W1, const float* __restrict__ b1, const float* __restrict__ g1, const float* __restrict__ gb1, const float* __restrict__ hb1,
    const float* __restrict__ W2, const float* __restrict__ b2, const float* __restrict__ g2, const float* __restrict__ gb2, const float* __restrict__ hb2,
    const float* __restrict__ W3, const float* __restrict__ b3, const float* __restrict__ g3, const float* __restrict__ gb3, const float* __restrict__ hb3)
{
    const int tt = blockIdx.x;
    const float ts0 = ts[0], ts1 = ts[1], ts2 = ts[2];
    float t;
    if (tt == 0) t = ts0;
    else if (tt == 1) t = ts0 + 0.5f * (ts1 - ts0);
    else if (tt == 2) t = ts1;
    else if (tt == 3) t = ts1 + 0.5f * (ts2 - ts1);
    else t = ts2;

    float* tf = g_Tf + tt * TF_FLOATS;
    __half* hp = g_Thf + (size_t)tt * 2 * BP_ELEMS;
    __nv_bfloat16* fw = g_FWb + (size_t)tt * FB_BF;
    float* fc = g_FWc + tt * FB_CF;
    const int tid = threadIdx.x;

    for (int i = tid; i < 1024; i += blockDim.x) {
        int j = i >> 6, c = i & 63;
        float v = W0[i] * sigm(t * g0[c] + gb0[c]);
        tf[j * TF_STRIDE + c] = v;
        __nv_bfloat16 h = __float2bfloat16_rn(v);
        __nv_bfloat16 l = __float2bfloat16_rn(v - __bfloat162float(h));
        fw[FB_W0H + j * 72 + c] = h;
        fw[FB_W0L + j * 72 + c] = l;
    }
    for (int i = tid; i < 4096; i += blockDim.x) {
        int a = i >> 6, b = i & 63;
        float v = W1[i] * sigm(t * g1[b] + gb1[b]);
        __nv_bfloat16 h = __float2bfloat16_rn(v);
        __nv_bfloat16 l = __float2bfloat16_rn(v - __bfloat162float(h));
        fw[FB_W1H + a * 72 + b] = h;
        fw[FB_W1L + a * 72 + b] = l;
        hp[0 * BP_ELEMS + a * BP_STRIDE + b] = __float2half_rn(v);
    }
    for (int i = tid; i < 4096; i += blockDim.x) {
        int b = i >> 6, c = i & 63;
        float v = W2[i] * sigm(t * g2[c] + gb2[c]);
        __nv_bfloat16 h = __float2bfloat16_rn(v);
        __nv_bfloat16 l = __float2bfloat16_rn(v - __bfloat162float(h));
        fw[FB_W2H + b * 72 + c] = h;
        fw[FB_W2L + b * 72 + c] = l;
        hp[1 * BP_ELEMS + c * BP_STRIDE + b] = __float2half_rn(v);
    }
    for (int i = tid; i < 1024; i += blockDim.x) {
        int j = i >> 4, e = i & 15;
        float v = W3[i] * sigm(t * g3[e] + gb3[e]);
        tf[TF_M3T + e * TF_STRIDE + j] = v;
        __nv_bfloat16 h = __float2bfloat16_rn(v);
        __nv_bfloat16 l = __float2bfloat16_rn(v - __bfloat162float(h));
        fw[FB_W3H + j * 24 + e] = h;
        fw[FB_W3L + j * 24 + e] = l;
    }
    if (tid < 64) {
        float s0 = sigm(t * g0[tid] + gb0[tid]);
        float s1 = sigm(t * g1[tid] + gb1[tid]);
        float s2 = sigm(t * g2[tid] + gb2[tid]);
        fc[0 + tid]   = b0[tid] * s0 + t * hb0[tid];
        fc[64 + tid]  = b1[tid] * s1 + t * hb1[tid];
        fc[128 + tid] = b2[tid] * s2 + t * hb2[tid];
        if (tid < 16) {
            float s3 = sigm(t * g3[tid] + gb3[tid]);
            fc[192 + tid] = b3[tid] * s3 + t * hb3[tid];
        }
    }
}

// ================= forward kernel =================
__device__ __forceinline__ void fwd_epi(const float* acc, const float* Cv,
                                        float* stg, int g, int tig,
                                        uint32_t* fh, uint32_t* fl)
{
    #pragma unroll
    for (int nt = 0; nt < 8; ++nt) {
        const int col = nt * 8 + 2 * tig;
        const float b0 = Cv[col], b1 = Cv[col + 1];
        const float h0 = tanh_f(acc[nt * 4 + 0] + b0);
        const float h1 = tanh_f(acc[nt * 4 + 1] + b1);
        const float h2 = tanh_f(acc[nt * 4 + 2] + b0);
        const float h3 = tanh_f(acc[nt * 4 + 3] + b1);
        *(float2*)(stg + g * STG_STRIDE + col)       = make_float2(1.f - h0 * h0, 1.f - h1 * h1);
        *(float2*)(stg + (g + 8) * STG_STRIDE + col) = make_float2(1.f - h2 * h2, 1.f - h3 * h3);
        const int kk = nt >> 1, hf = nt & 1;
        fh[kk * 4 + hf * 2 + 0] = bf2_split(h0, h1, fl[kk * 4 + hf * 2 + 0]);
        fh[kk * 4 + hf * 2 + 1] = bf2_split(h2, h3, fl[kk * 4 + hf * 2 + 1]);
    }
}

__device__ __forceinline__ void stage_flush(const float* stg, float* dst, int lane)
{
    #pragma unroll
    for (int k = 0; k < 8; ++k) {
        const int idx4 = lane + k * 32;
        const int row = idx4 >> 4, c4 = idx4 & 15;
        *(float4*)(dst + row * 192 + c4 * 4) = *(const float4*)(stg + row * STG_STRIDE + c4 * 4);
    }
}

__global__ __launch_bounds__(FNT, 2)
void forward_kernel(const float* __restrict__ ts, const float* __restrict__ x0,
                    float* __restrict__ out)
{
    extern __shared__ char smc[];
    float* C = (float*)(smc + FB_BYTES_BF);
    float* stage = (float*)(smc + FB_BYTES_BF + FB_CF * 4);

    const int tid  = threadIdx.x;
    const int lane = tid & 31;
    const int wid  = tid >> 5;
    const int g = lane >> 2, tig = lane & 3;
    const int d0c = 2 * tig, d1c = 8 + 2 * tig;

    float* stg = stage + wid * STG_WARP;
    const int rowbase = blockIdx.x * FROWS + wid * 16;
    const int rowA = rowbase + g;
    const int rowB = rowA + 8;

    const uint32_t smb = smem_u32(smc);
    const uint32_t lrow = lane & 15, lcol = (lane >> 4) * 16;

    const float ts0 = ts[0], ts1 = ts[1], ts2 = ts[2];
    const float tst[3] = {ts0, ts1, ts2};

    float xs[8];
    {
        float2 p0 = *(const float2*)(x0 + rowA * 16 + d0c);
        float2 p1 = *(const float2*)(x0 + rowB * 16 + d0c);
        float2 p2 = *(const float2*)(x0 + rowA * 16 + d1c);
        float2 p3 = *(const float2*)(x0 + rowB * 16 + d1c);
        xs[0] = p0.x; xs[1] = p0.y; xs[2] = p1.x; xs[3] = p1.y;
        xs[4] = p2.x; xs[5] = p2.y; xs[6] = p3.x; xs[7] = p3.y;
        *(float2*)(out + rowA * 16 + d0c) = p0;
        *(float2*)(out + rowB * 16 + d0c) = p1;
        *(float2*)(out + rowA * 16 + d1c) = p2;
        *(float2*)(out + rowB * 16 + d1c) = p3;
    }
    float vA = 0.f, vB = 0.f;
    int ptt = -1;

    // zero log_det accumulation slots (tangent kernel atomically adds into them)
    if (tig == 0) {
        out[3 * BATCH * Dd + rowA] = 0.f;
        out[3 * BATCH * Dd + rowB] = 0.f;
    }

    #pragma unroll 1
    for (int step = 0; step < 2; ++step) {
        const float tA = tst[step];
        const float hstep = tst[step + 1] - tA;
        float ksx[8], kxp[8];
        #pragma unroll
        for (int i = 0; i < 8; ++i) { ksx[i] = 0.f; kxp[i] = 0.f; }
        float ksvA = 0.f, ksvB = 0.f;

        #pragma unroll 1
        for (int stage_i = 0; stage_i < 4; ++stage_i) {
            const int tt = step * 2 + ((stage_i == 0) ? 0 : ((stage_i == 3) ? 2 : 1));
            if (tt != ptt) {
                __syncthreads();
                const uint4* src = (const uint4*)(g_FWb + (size_t)tt * FB_BF);
                uint4* dst = (uint4*)smc;
                #pragma unroll 4
                for (int i = tid; i < FB_BYTES_BF / 16; i += FNT) dst[i] = __ldg(src + i);
                const uint4* cs = (const uint4*)(g_FWc + tt * FB_CF);
                uint4* cd = (uint4*)(smc + FB_BYTES_BF);
                if (tid < FB_CF / 4) cd[tid] = __ldg(cs + tid);
                __syncthreads();
                ptt = tt;
            }
            const int e = step * 4 + stage_i;
            const float coef = (stage_i == 0) ? 0.f : ((stage_i == 3) ? hstep : 0.5f * hstep);
            const float wq = (stage_i == 1 || stage_i == 2) ? 2.f : 1.f;

            float* gdw = g_d + ((size_t)e * BATCH + rowbase) * 192;

            uint32_t fh[16], fl[16];
            {
                float xe[8];
                #pragma unroll
                for (int i = 0; i < 8; ++i) xe[i] = xs[i] + coef * kxp[i];
                fh[0] = bf2_split(xe[0], xe[1], fl[0]);
                fh[1] = bf2_split(xe[2], xe[3], fl[1]);
                fh[2] = bf2_split(xe[4], xe[5], fl[2]);
                fh[3] = bf2_split(xe[6], xe[7], fl[3]);
            }
            float acc[32];

            // ---- L0 ----
            #pragma unroll
            for (int i = 0; i < 32; ++i) acc[i] = 0.f;
            {
                const uint32_t rb_ = smb + FB_W0H * 2 + lrow * 144 + lcol;
                #pragma unroll
                for (int p = 0; p < 4; ++p) {
                    uint32_t h0, h1, h2, h3, l0, l1, l2, l3;
                    ldmx4(rb_ + p * 32, h0, h1, h2, h3);
                    ldmx4(rb_ + p * 32 + 2304, l0, l1, l2, l3);
                    mma3(acc + (2 * p) * 4, fh, fl, h0, h1, l0, l1);
                    mma3(acc + (2 * p + 1) * 4, fh, fl, h2, h3, l2, l3);
                }
            }
            fwd_epi(acc, C + 0, stg, g, tig, fh, fl);
            __syncwarp();
            stage_flush(stg, gdw + 0, lane);
            __syncwarp();

            // ---- L1 ----
            #pragma unroll
            for (int i = 0; i < 32; ++i) acc[i] = 0.f;
            {
                const uint32_t rb_ = smb + FB_W1H * 2 + lrow * 144 + lcol;
                #pragma unroll
                for (int kk = 0; kk < 4; ++kk) {
                    const uint32_t rk = rb_ + kk * 16 * 144;
                    #pragma unroll
                    for (int p = 0; p < 4; ++p) {
                        uint32_t h0, h1, h2, h3, l0, l1, l2, l3;
                        ldmx4(rk + p * 32, h0, h1, h2, h3);
                        ldmx4(rk + p * 32 + 9216, l0, l1, l2, l3);
                        mma3(acc + (2 * p) * 4, fh + kk * 4, fl + kk * 4, h0, h1, l0, l1);
                        mma3(acc + (2 * p + 1) * 4, fh + kk * 4, fl + kk * 4, h2, h3, l2, l3);
                    }
                }
            }
            fwd_epi(acc, C + 64, stg, g, tig, fh, fl);
            __syncwarp();
            stage_flush(stg, gdw + 64, lane);
            __syncwarp();

            // ---- L2 ----
            #pragma unroll
            for (int i = 0; i < 32; ++i) acc[i] = 0.f;
            {
                const uint32_t rb_ = smb + FB_W2H * 2 + lrow * 144 + lcol;
                #pragma unroll
                for (int kk = 0; kk < 4; ++kk) {
                    const uint32_t rk = rb_ + kk * 16 * 144;
                    #pragma unroll
                    for (int p = 0; p < 4; ++p) {
                        uint32_t h0, h1, h2, h3, l0, l1, l2, l3;
                        ldmx4(rk + p * 32, h0, h1, h2, h3);
                        ldmx4(rk + p * 32 + 9216, l0, l1, l2, l3);
                        mma3(acc + (2 * p) * 4, fh + kk * 4, fl + kk * 4, h0, h1, l0, l1);
                        mma3(acc + (2 * p + 1) * 4, fh + kk * 4, fl + kk * 4, h2, h3, l2, l3);
                    }
                }
            }
            fwd_epi(acc, C + 128, stg, g, tig, fh, fl);
            __syncwarp();
            stage_flush(stg, gdw + 128, lane);
            __syncwarp();

            // ---- L3 ----
            float a3[8];
            #pragma unroll
            for (int i = 0; i < 8; ++i) a3[i] = 0.f;
            {
                const uint32_t rb_ = smb + FB_W3H * 2 + lrow * 48 + lcol;
                #pragma unroll
                for (int kk = 0; kk < 4; ++kk) {
                    uint32_t h0, h1, h2, h3, l0, l1, l2, l3;
                    ldmx4(rb_ + kk * 16 * 48, h0, h1, h2, h3);
                    ldmx4(rb_ + kk * 16 * 48 + 3072, l0, l1, l2, l3);
                    mma3(a3 + 0, fh + kk * 4, fl + kk * 4, h0, h1, l0, l1);
                    mma3(a3 + 4, fh + kk * 4, fl + kk * 4, h2, h3, l2, l3);
                }
            }
            float dxv[8];
            dxv[0] = a3[0] + C[192 + d0c];  dxv[1] = a3[1] + C[192 + d0c + 1];
            dxv[2] = a3[2] + C[192 + d0c];  dxv[3] = a3[3] + C[192 + d0c + 1];
            dxv[4] = a3[4] + C[192 + d1c];  dxv[5] = a3[5] + C[192 + d1c + 1];
            dxv[6] = a3[6] + C[192 + d1c];  dxv[7] = a3[7] + C[192 + d1c + 1];

            float dvA = dxv[0] * dxv[0] + dxv[1] * dxv[1] + dxv[4] * dxv[4] + dxv[5] * dxv[5];
            float dvB = dxv[2] * dxv[2] + dxv[3] * dxv[3] + dxv[6] * dxv[6] + dxv[7] * dxv[7];
            dvA += __shfl_xor_sync(0xffffffffu, dvA, 1);
            dvA += __shfl_xor_sync(0xffffffffu, dvA, 2);
            dvB += __shfl_xor_sync(0xffffffffu, dvB, 1);
            dvB += __shfl_xor_sync(0xffffffffu, dvB, 2);

            #pragma unroll
            for (int i = 0; i < 8; ++i) { ksx[i] += wq * dxv[i]; kxp[i] = dxv[i]; }
            ksvA += wq * dvA;
            ksvB += wq * dvB;
        }

        const float scl = hstep * (1.f / 6.f);
        #pragma unroll
        for (int i = 0; i < 8; ++i) xs[i] += scl * ksx[i];
        vA += scl * 0.5f * ksvA;
        vB += scl * 0.5f * ksvB;

        float* os = out + (step + 1) * BATCH * Dd;
        *(float2*)(os + rowA * 16 + d0c) = make_float2(xs[0], xs[1]);
        *(float2*)(os + rowB * 16 + d0c) = make_float2(xs[2], xs[3]);
        *(float2*)(os + rowA * 16 + d1c) = make_float2(xs[4], xs[5]);
        *(float2*)(os + rowB * 16 + d1c) = make_float2(xs[6], xs[7]);
    }

    if (tig == 0) {
        const int base = 3 * BATCH * Dd;
        out[base + BATCH + rowA] = fabsf(vA);
        out[base + BATCH + rowB] = fabsf(vB);
        out[base + 2 * BATCH + rowA] = 0.f;
        out[base + 2 * BATCH + rowB] = 0.f;
    }
}

// ================= tangent kernel (fp16 mma, interleaved GEMMs, fused combine) =================
#define TS_TF 4608
#define TS_DV (TS_TF + TF_FLOATS)
#define TS_FLOATS (TS_DV + 64 * 192)
#define TS_BYTES (TS_FLOATS * 4)

__global__ __launch_bounds__(256, 2)
void tangent_kernel(const float* __restrict__ ts, float* __restrict__ out)
{
    extern __shared__ float sm[];
    const int tid = threadIdx.x;
    const int lane = tid & 31;
    const int wid = tid >> 5;

    const int e = blockIdx.x >> 9;
    const int rg = blockIdx.x & 511;
    const int row0 = rg * 64;
    const int tmap[8] = {0, 1, 1, 2, 2, 3, 3, 4};
    const int tt = tmap[e];

    // RK4 weight for this eval
    const int stp = e >> 2, stg_i = e & 3;
    const float hstep = ts[stp + 1] - ts[stp];
    const float wrk = (hstep * (1.f / 6.f)) * ((stg_i == 1 || stg_i == 2) ? 2.f : 1.f);

    {
        const uint4* bsrc = (const uint4*)(g_Thf + (size_t)tt * 2 * BP_ELEMS);
        uint4* bdst = (uint4*)sm;
        #pragma unroll 4
        for (int i = tid; i < (2 * BP_ELEMS * 2) / 16; i += 256) bdst[i] = __ldg(bsrc + i);
        const uint4* fsrc = (const uint4*)(g_Tf + tt * TF_FLOATS);
        uint4* fdst = (uint4*)(sm + TS_TF);
        #pragma unroll 2
        for (int i = tid; i < TF_FLOATS / 4; i += 256) fdst[i] = __ldg(fsrc + i);
        const uint4* dsrc = (const uint4*)(g_d + ((size_t)e * BATCH + row0) * 192);
        uint4* ddst = (uint4*)(sm + TS_DV);
        #pragma unroll 4
        for (int i = tid; i < (64 * 192) / 4; i += 256) ddst[i] = __ldg(dsrc + i);
    }
    __syncthreads();

    const uint32_t smbB = smem_u32(sm);
    const float* M0f = sm + TS_TF;
    const float* M3T = sm + TS_TF + TF_M3T;

    const int g = lane >> 2;
    const int k0 = (lane & 3) * 2;
    const uint32_t lrow = lane & 15, lcol = (lane >> 4) * 16;

    #pragma unroll 1
    for (int rl = 0; rl < 8; ++rl) {
        const int r = wid * 8 + rl;
        const float* d0p = sm + TS_DV + r * 192;
        const float* d1p = d0p + 64;
        const float* d2p = d0p + 128;

        float acc1[32], acc2[32];
        #pragma unroll
        for (int i = 0; i < 32; ++i) { acc1[i] = 0.f; acc2[i] = 0.f; }

        // ---- interleaved GEMM1/GEMM2 per K chunk ----
        #pragma unroll
        for (int kk = 0; kk < 4; ++kk) {
            const int K = kk * 16;
            // GEMM1: U2 = (M0f .* d0) @ B1
            {
                const float2 dA = *(const float2*)(d0p + K + k0);
                const float2 dB = *(const float2*)(d0p + K + k0 + 8);
                const float2 mA = *(const float2*)(M0f + g * TF_STRIDE + K + k0);
                const float2 mB = *(const float2*)(M0f + (g + 8) * TF_STRIDE + K + k0);
                const float2 mC = *(const float2*)(M0f + g * TF_STRIDE + K + k0 + 8);
                const float2 mD = *(const float2*)(M0f + (g + 8) * TF_STRIDE + K + k0 + 8);
                uint32_t ah[4];
                ah[0] = f16pk(mA.x * dA.x, mA.y * dA.y);
                ah[1] = f16pk(mB.x * dA.x, mB.y * dA.y);
                ah[2] = f16pk(mC.x * dB.x, mC.y * dB.y);
                ah[3] = f16pk(mD.x * dB.x, mD.y * dB.y);
                const uint32_t rowaddr = smbB + (K + lrow) * (BP_STRIDE * 2) + lcol;
                #pragma unroll
                for (int p = 0; p < 4; ++p) {
                    uint32_t h0, h1, h2, h3;
                    ldmx4(rowaddr + p * 32, h0, h1, h2, h3);
                    mma16816h(acc1 + (2 * p) * 4, ah, h0, h1);
                    mma16816h(acc1 + (2 * p + 1) * 4, ah, h2, h3);
                }
            }
            // GEMM2: W = (M3T .* d2) @ B2
            {
                const float2 dA = *(const float2*)(d2p + K + k0);
                const float2 dB = *(const float2*)(d2p + K + k0 + 8);
                const float2 mA = *(const float2*)(M3T + g * TF_STRIDE + K + k0);
                const float2 mB = *(const float2*)(M3T + (g + 8) * TF_STRIDE + K + k0);
                const float2 mC = *(const float2*)(M3T + g * TF_STRIDE + K + k0 + 8);
                const float2 mD = *(const float2*)(M3T + (g + 8) * TF_STRIDE + K + k0 + 8);
                uint32_t ah[4];
                ah[0] = f16pk(mA.x * dA.x, mA.y * dA.y);
                ah[1] = f16pk(mB.x * dA.x, mB.y * dA.y);
                ah[2] = f16pk(mC.x * dB.x, mC.y * dB.y);
                ah[3] = f16pk(mD.x * dB.x, mD.y * dB.y);
                const uint32_t rowaddr = smbB + (K + lrow) * (BP_STRIDE * 2) + lcol + BP_ELEMS * 2;
                #pragma unroll
                for (int p = 0; p < 4; ++p) {
                    uint32_t h0, h1, h2, h3;
                    ldmx4(rowaddr + p * 32, h0, h1, h2, h3);
                    mma16816h(acc2 + (2 * p) * 4, ah, h0, h1);
                    mma16816h(acc2 + (2 * p + 1) * 4, ah, h2, h3);
                }
            }
        }

        // ---- dl = sum U2 .* d1 .* W ----
        float dl = 0.f;
        #pragma unroll
        for (int nt = 0; nt < 8; ++nt) {
            const float2 dp = *(const float2*)(d1p + nt * 8 + k0);
            dl = fmaf(acc1[nt * 4 + 0] * dp.x, acc2[nt * 4 + 0], dl);
            dl = fmaf(acc1[nt * 4 + 1] * dp.y, acc2[nt * 4 + 1], dl);
            dl = fmaf(acc1[nt * 4 + 2] * dp.x, acc2[nt * 4 + 2], dl);
            dl = fmaf(acc1[nt * 4 + 3] * dp.y, acc2[nt * 4 + 3], dl);
        }
        #pragma unroll
        for (int m = 1; m <= 16; m <<= 1)
            dl += __shfl_xor_sync(0xffffffffu, dl, m);
        if (lane == 0)
            atomicAdd(out + 3 * BATCH * Dd + row0 + r, wrk * dl);
    }
}

extern "C" void kernel_launch(void* const* d_in, const int* in_sizes, int n_in,
                              void* d_out, int out_size) {
    const float* ts  = (const float*)d_in[0];
    const float* x0  = (const float*)d_in[1];
    const float* W0  = (const float*)d_in[2];
    const float* b0  = (const float*)d_in[3];
    const float* g0  = (const float*)d_in[4];
    const float* gb0 = (const float*)d_in[5];
    const float* hb0 = (const float*)d_in[6];
    const float* W1  = (const float*)d_in[7];
    const float* b1  = (const float*)d_in[8];
    const float* g1  = (const float*)d_in[9];
    const float* gb1 = (const float*)d_in[10];
    const float* hb1 = (const float*)d_in[11];
    const float* W2  = (const float*)d_in[12];
    const float* b2  = (const float*)d_in[13];
    const float* g2  = (const float*)d_in[14];
    const float* gb2 = (const float*)d_in[15];
    const float* hb2 = (const float*)d_in[16];
    const float* W3  = (const float*)d_in[17];
    const float* b3  = (const float*)d_in[18];
    const float* g3  = (const float*)d_in[19];
    const float* gb3 = (const float*)d_in[20];
    const float* hb3 = (const float*)d_in[21];
    float* out = (float*)d_out;

    build_kernel<<<NT, 256>>>(ts,
        W0, b0, g0, gb0, hb0,
        W1, b1, g1, gb1, hb1,
        W2, b2, g2, gb2, hb2,
        W3, b3, g3, gb3, hb3);

    cudaFuncSetAttribute(forward_kernel, cudaFuncAttributeMaxDynamicSharedMemorySize, FWD_SMEM);
    forward_kernel<<<BATCH / FROWS, FNT, FWD_SMEM>>>(ts, x0, out);

    cudaFuncSetAttribute(tangent_kernel, cudaFuncAttributeMaxDynamicSharedMemorySize, TS_BYTES);
    tangent_kernel<<<8 * 512, 256, TS_BYTES>>>(ts, out);
}

// round 14
// speedup vs baseline: 1.7326x; 1.0715x over previous
#include <cuda_runtime.h>
#include <cuda_bf16.h>
#include <cuda_fp16.h>
#include <cstdint>

#define Dd 16
#define BATCH 32768

typedef unsigned long long ull;

#define NT 5   // distinct t values

// -------- tangent-kernel constants --------
#define TF_STRIDE 68
#define TF_M3T    (16 * TF_STRIDE)
#define TF_FLOATS (2 * 16 * TF_STRIDE)
#define BP_STRIDE 72
#define BP_ELEMS  (64 * BP_STRIDE)

// -------- forward-kernel bf16 weight planes (per t), element offsets --------
#define FB_W0H 0
#define FB_W0L 1152
#define FB_W1H 2304
#define FB_W1L 6912
#define FB_W2H 11520
#define FB_W2L 16128
#define FB_W3H 20736
#define FB_W3L 22272
#define FB_BF  23808
#define FB_BYTES_BF (FB_BF * 2)
#define FB_CF  208
#define STG_STRIDE 68
#define STG_WARP   (16 * STG_STRIDE)
#define FNWARP 8
#define FNT    (FNWARP * 32)
#define FROWS  (FNWARP * 16)
#define FWD_SMEM (FB_BYTES_BF + FB_CF * 4 + FNWARP * STG_WARP * 4)

__device__ __align__(16) float g_Tf[NT * TF_FLOATS];
__device__ __align__(16) __half g_Thf[NT * 2 * BP_ELEMS];   // fp16 B planes: B1, B2
__device__ __align__(16) __nv_bfloat16 g_FWb[NT * FB_BF];
__device__ __align__(16) float g_FWc[NT * FB_CF];
__device__ float g_d[8ull * BATCH * 192];

__device__ __forceinline__ float sigm(float x) {
    return __fdividef(1.f, 1.f + __expf(-x));
}
__device__ __forceinline__ float tanh_f(float x) {
    x = fminf(fmaxf(x, -15.f), 15.f);
    float e = __expf(-2.f * x);
    return __fdividef(1.f - e, 1.f + e);
}
__device__ __forceinline__ uint32_t smem_u32(const void* p) {
    uint32_t a;
    asm("{ .reg .u64 t; cvta.to.shared.u64 t, %1; cvt.u32.u64 %0, t; }" : "=r"(a) : "l"(p));
    return a;
}
__device__ __forceinline__ void cpa16(uint32_t s, const void* g) {
    asm volatile("cp.async.cg.shared.global [%0], [%1], 16;" :: "r"(s), "l"(g));
}
__device__ __forceinline__ void cpa_commit_wait() {
    asm volatile("cp.async.commit_group;");
    asm volatile("cp.async.wait_group 0;" ::: "memory");
}
__device__ __forceinline__ uint32_t bf2_split(float v0, float v1, uint32_t& lo) {
    uint32_t h;
    asm("cvt.rn.bf16x2.f32 %0, %1, %2;" : "=r"(h) : "f"(v1), "f"(v0));
    float r0 = v0 - __uint_as_float(h << 16);
    float r1 = v1 - __uint_as_float(h & 0xFFFF0000u);
    asm("cvt.rn.bf16x2.f32 %0, %1, %2;" : "=r"(lo) : "f"(r1), "f"(r0));
    return h;
}
__device__ __forceinline__ uint32_t f16pk(float v0, float v1) {
    uint32_t r;
    asm("cvt.rn.f16x2.f32 %0, %1, %2;" : "=r"(r) : "f"(v1), "f"(v0));
    return r;
}
__device__ __forceinline__ void ldmx4(uint32_t addr, uint32_t& r0, uint32_t& r1,
                                      uint32_t& r2, uint32_t& r3) {
    asm volatile("ldmatrix.sync.aligned.m8n8.x4.trans.shared.b16 {%0,%1,%2,%3}, [%4];"
                 : "=r"(r0), "=r"(r1), "=r"(r2), "=r"(r3) : "r"(addr));
}
__device__ __forceinline__ void mma16816(float* c, const uint32_t* a, uint32_t b0, uint32_t b1) {
    asm("mma.sync.aligned.m16n8k16.row.col.f32.bf16.bf16.f32 "
        "{%0,%1,%2,%3}, {%4,%5,%6,%7}, {%8,%9}, {%0,%1,%2,%3};"
        : "+f"(c[0]), "+f"(c[1]), "+f"(c[2]), "+f"(c[3])
        : "r"(a[0]), "r"(a[1]), "r"(a[2]), "r"(a[3]), "r"(b0), "r"(b1));
}
__device__ __forceinline__ void mma16816h(float* c, const uint32_t* a, uint32_t b0, uint32_t b1) {
    asm("mma.sync.aligned.m16n8k16.row.col.f32.f16.f16.f32 "
        "{%0,%1,%2,%3}, {%4,%5,%6,%7}, {%8,%9}, {%0,%1,%2,%3};"
        : "+f"(c[0]), "+f"(c[1]), "+f"(c[2]), "+f"(c[3])
        : "r"(a[0]), "r"(a[1]), "r"(a[2]), "r"(a[3]), "r"(b0), "r"(b1));
}
__device__ __forceinline__ void mma3(float* c, const uint32_t* ah, const uint32_t* al,
                                     uint32_t bh0, uint32_t bh1, uint32_t bl0, uint32_t bl1) {
    mma16816(c, ah, bh0, bh1);
    mma16816(c, al, bh0, bh1);
    mma16816(c, ah, bl0, bl1);
}

// ---------------- build kernel: 8 slices per distinct t (grid = NT*8) ----------------
__global__ void build_kernel(const float* __restrict__ ts,
    const float* __restrict__ W0, const float* __restrict__ b0, const float* __restrict__ g0, const float* __restrict__ gb0, const float* __restrict__ hb0,
    const float* __restrict__ W1, const float* __restrict__ b1, const float* __restrict__ g1, const float* __restrict__ gb1, const float* __restrict__ hb1,
    const float* __restrict__ W2, const float* __restrict__ b2, const float* __restrict__ g2, const float* __restrict__ gb2, const float* __restrict__ hb2,
    const float* __restrict__ W3, const float* __restrict__ b3, const float* __restrict__ g3, const float* __restrict__ gb3, const float* __restrict__ hb3)
{
    const int tt = blockIdx.x >> 3;
    const int sl = blockIdx.x & 7;
    const float ts0 = ts[0], ts1 = ts[1], ts2 = ts[2];
    float t;
    if (tt == 0) t = ts0;
    else if (tt == 1) t = ts0 + 0.5f * (ts1 - ts0);
    else if (tt == 2) t = ts1;
    else if (tt == 3) t = ts1 + 0.5f * (ts2 - ts1);
    else t = ts2;

    float* tf = g_Tf + tt * TF_FLOATS;
    __half* hp = g_Thf + (size_t)tt * 2 * BP_ELEMS;
    __nv_bfloat16* fw = g_FWb + (size_t)tt * FB_BF;
    float* fc = g_FWc + tt * FB_CF;
    const int tid = threadIdx.x;

    for (int i = sl * 128 + tid; i < (sl + 1) * 128; i += blockDim.x) {
        int j = i >> 6, c = i & 63;
        float v = W0[i] * sigm(t * g0[c] + gb0[c]);
        tf[j * TF_STRIDE + c] = v;
        __nv_bfloat16 h = __float2bfloat16_rn(v);
        __nv_bfloat16 l = __float2bfloat16_rn(v - __bfloat162float(h));
        fw[FB_W0H + j * 72 + c] = h;
        fw[FB_W0L + j * 72 + c] = l;
    }
    for (int i = sl * 512 + tid; i < (sl + 1) * 512; i += blockDim.x) {
        int a = i >> 6, b = i & 63;
        float v = W1[i] * sigm(t * g1[b] + gb1[b]);
        __nv_bfloat16 h = __float2bfloat16_rn(v);
        __nv_bfloat16 l = __float2bfloat16_rn(v - __bfloat162float(h));
        fw[FB_W1H + a * 72 + b] = h;
        fw[FB_W1L + a * 72 + b] = l;
        hp[0 * BP_ELEMS + a * BP_STRIDE + b] = __float2half_rn(v);
    }
    for (int i = sl * 512 + tid; i < (sl + 1) * 512; i += blockDim.x) {
        int b = i >> 6, c = i & 63;
        float v = W2[i] * sigm(t * g2[c] + gb2[c]);
        __nv_bfloat16 h = __float2bfloat16_rn(v);
        __nv_bfloat16 l = __float2bfloat16_rn(v - __bfloat162float(h));
        fw[FB_W2H + b * 72 + c] = h;
        fw[FB_W2L + b * 72 + c] = l;
        hp[1 * BP_ELEMS + c * BP_STRIDE + b] = __float2half_rn(v);
    }
    for (int i = sl * 128 + tid; i < (sl + 1) * 128; i += blockDim.x) {
        int j = i >> 4, e = i & 15;
        float v = W3[i] * sigm(t * g3[e] + gb3[e]);
        tf[TF_M3T + e * TF_STRIDE + j] = v;
        __nv_bfloat16 h = __float2bfloat16_rn(v);
        __nv_bfloat16 l = __float2bfloat16_rn(v - __bfloat162float(h));
        fw[FB_W3H + j * 24 + e] = h;
        fw[FB_W3L + j * 24 + e] = l;
    }
    if (sl == 0 && tid < 64) {
        float s0 = sigm(t * g0[tid] + gb0[tid]);
        float s1 = sigm(t * g1[tid] + gb1[tid]);
        float s2 = sigm(t * g2[tid] + gb2[tid]);
        fc[0 + tid]   = b0[tid] * s0 + t * hb0[tid];
        fc[64 + tid]  = b1[tid] * s1 + t * hb1[tid];
        fc[128 + tid] = b2[tid] * s2 + t * hb2[tid];
        if (tid < 16) {
            float s3 = sigm(t * g3[tid] + gb3[tid]);
            fc[192 + tid] = b3[tid] * s3 + t * hb3[tid];
        }
    }
}

// ================= forward kernel =================
__device__ __forceinline__ void fwd_epi(const float* acc, const float* Cv,
                                        float* stg, int g, int tig,
                                        uint32_t* fh, uint32_t* fl)
{
    #pragma unroll
    for (int nt = 0; nt < 8; ++nt) {
        const int col = nt * 8 + 2 * tig;
        const float b0 = Cv[col], b1 = Cv[col + 1];
        const float h0 = tanh_f(acc[nt * 4 + 0] + b0);
        const float h1 = tanh_f(acc[nt * 4 + 1] + b1);
        const float h2 = tanh_f(acc[nt * 4 + 2] + b0);
        const float h3 = tanh_f(acc[nt * 4 + 3] + b1);
        *(float2*)(stg + g * STG_STRIDE + col)       = make_float2(1.f - h0 * h0, 1.f - h1 * h1);
        *(float2*)(stg + (g + 8) * STG_STRIDE + col) = make_float2(1.f - h2 * h2, 1.f - h3 * h3);
        const int kk = nt >> 1, hf = nt & 1;
        fh[kk * 4 + hf * 2 + 0] = bf2_split(h0, h1, fl[kk * 4 + hf * 2 + 0]);
        fh[kk * 4 + hf * 2 + 1] = bf2_split(h2, h3, fl[kk * 4 + hf * 2 + 1]);
    }
}

__device__ __forceinline__ void stage_flush(const float* stg, float* dst, int lane)
{
    #pragma unroll
    for (int k = 0; k < 8; ++k) {
        const int idx4 = lane + k * 32;
        const int row = idx4 >> 4, c4 = idx4 & 15;
        *(float4*)(dst + row * 192 + c4 * 4) = *(const float4*)(stg + row * STG_STRIDE + c4 * 4);
    }
}

__global__ __launch_bounds__(FNT, 2)
void forward_kernel(const float* __restrict__ ts, const float* __restrict__ x0,
                    float* __restrict__ out)
{
    extern __shared__ char smc[];
    float* C = (float*)(smc + FB_BYTES_BF);
    float* stage = (float*)(smc + FB_BYTES_BF + FB_CF * 4);

    const int tid  = threadIdx.x;
    const int lane = tid & 31;
    const int wid  = tid >> 5;
    const int g = lane >> 2, tig = lane & 3;
    const int d0c = 2 * tig, d1c = 8 + 2 * tig;

    float* stg = stage + wid * STG_WARP;
    const int rowbase = blockIdx.x * FROWS + wid * 16;
    const int rowA = rowbase + g;
    const int rowB = rowA + 8;

    const uint32_t smb = smem_u32(smc);
    const uint32_t lrow = lane & 15, lcol = (lane >> 4) * 16;

    const float ts0 = ts[0], ts1 = ts[1], ts2 = ts[2];
    const float tst[3] = {ts0, ts1, ts2};

    float xs[8];
    {
        float2 p0 = *(const float2*)(x0 + rowA * 16 + d0c);
        float2 p1 = *(const float2*)(x0 + rowB * 16 + d0c);
        float2 p2 = *(const float2*)(x0 + rowA * 16 + d1c);
        float2 p3 = *(const float2*)(x0 + rowB * 16 + d1c);
        xs[0] = p0.x; xs[1] = p0.y; xs[2] = p1.x; xs[3] = p1.y;
        xs[4] = p2.x; xs[5] = p2.y; xs[6] = p3.x; xs[7] = p3.y;
        *(float2*)(out + rowA * 16 + d0c) = p0;
        *(float2*)(out + rowB * 16 + d0c) = p1;
        *(float2*)(out + rowA * 16 + d1c) = p2;
        *(float2*)(out + rowB * 16 + d1c) = p3;
    }
    float vA = 0.f, vB = 0.f;
    int ptt = -1;

    if (tig == 0) {
        out[3 * BATCH * Dd + rowA] = 0.f;
        out[3 * BATCH * Dd + rowB] = 0.f;
    }

    #pragma unroll 1
    for (int step = 0; step < 2; ++step) {
        const float tA = tst[step];
        const float hstep = tst[step + 1] - tA;
        float ksx[8], kxp[8];
        #pragma unroll
        for (int i = 0; i < 8; ++i) { ksx[i] = 0.f; kxp[i] = 0.f; }
        float ksvA = 0.f, ksvB = 0.f;

        #pragma unroll 1
        for (int stage_i = 0; stage_i < 4; ++stage_i) {
            const int tt = step * 2 + ((stage_i == 0) ? 0 : ((stage_i == 3) ? 2 : 1));
            if (tt != ptt) {
                __syncthreads();
                const char* src = (const char*)(g_FWb + (size_t)tt * FB_BF);
                #pragma unroll 4
                for (int i = tid; i < FB_BYTES_BF / 16; i += FNT)
                    cpa16(smb + i * 16, src + i * 16);
                if (tid < FB_CF / 4)
                    cpa16(smb + FB_BYTES_BF + tid * 16,
                          (const char*)(g_FWc + tt * FB_CF) + tid * 16);
                cpa_commit_wait();
                __syncthreads();
                ptt = tt;
            }
            const int e = step * 4 + stage_i;
            const float coef = (stage_i == 0) ? 0.f : ((stage_i == 3) ? hstep : 0.5f * hstep);
            const float wq = (stage_i == 1 || stage_i == 2) ? 2.f : 1.f;

            float* gdw = g_d + ((size_t)e * BATCH + rowbase) * 192;

            uint32_t fh[16], fl[16];
            {
                float xe[8];
                #pragma unroll
                for (int i = 0; i < 8; ++i) xe[i] = xs[i] + coef * kxp[i];
                fh[0] = bf2_split(xe[0], xe[1], fl[0]);
                fh[1] = bf2_split(xe[2], xe[3], fl[1]);
                fh[2] = bf2_split(xe[4], xe[5], fl[2]);
                fh[3] = bf2_split(xe[6], xe[7], fl[3]);
            }
            float acc[32];

            // ---- L0 ----
            #pragma unroll
            for (int i = 0; i < 32; ++i) acc[i] = 0.f;
            {
                const uint32_t rb_ = smb + FB_W0H * 2 + lrow * 144 + lcol;
                #pragma unroll
                for (int p = 0; p < 4; ++p) {
                    uint32_t h0, h1, h2, h3, l0, l1, l2, l3;
                    ldmx4(rb_ + p * 32, h0, h1, h2, h3);
                    ldmx4(rb_ + p * 32 + 2304, l0, l1, l2, l3);
                    mma3(acc + (2 * p) * 4, fh, fl, h0, h1, l0, l1);
                    mma3(acc + (2 * p + 1) * 4, fh, fl, h2, h3, l2, l3);
                }
            }
            fwd_epi(acc, C + 0, stg, g, tig, fh, fl);
            __syncwarp();
            stage_flush(stg, gdw + 0, lane);
            __syncwarp();

            // ---- L1 ----
            #pragma unroll
            for (int i = 0; i < 32; ++i) acc[i] = 0.f;
            {
                const uint32_t rb_ = smb + FB_W1H * 2 + lrow * 144 + lcol;
                #pragma unroll
                for (int kk = 0; kk < 4; ++kk) {
                    const uint32_t rk = rb_ + kk * 16 * 144;
                    #pragma unroll
                    for (int p = 0; p < 4; ++p) {
                        uint32_t h0, h1, h2, h3, l0, l1, l2, l3;
                        ldmx4(rk + p * 32, h0, h1, h2, h3);
                        ldmx4(rk + p * 32 + 9216, l0, l1, l2, l3);
                        mma3(acc + (2 * p) * 4, fh + kk * 4, fl + kk * 4, h0, h1, l0, l1);
                        mma3(acc + (2 * p + 1) * 4, fh + kk * 4, fl + kk * 4, h2, h3, l2, l3);
                    }
                }
            }
            fwd_epi(acc, C + 64, stg, g, tig, fh, fl);
            __syncwarp();
            stage_flush(stg, gdw + 64, lane);
            __syncwarp();

            // ---- L2 ----
            #pragma unroll
            for (int i = 0; i < 32; ++i) acc[i] = 0.f;
            {
                const uint32_t rb_ = smb + FB_W2H * 2 + lrow * 144 + lcol;
                #pragma unroll
                for (int kk = 0; kk < 4; ++kk) {
                    const uint32_t rk = rb_ + kk * 16 * 144;
                    #pragma unroll
                    for (int p = 0; p < 4; ++p) {
                        uint32_t h0, h1, h2, h3, l0, l1, l2, l3;
                        ldmx4(rk + p * 32, h0, h1, h2, h3);
                        ldmx4(rk + p * 32 + 9216, l0, l1, l2, l3);
                        mma3(acc + (2 * p) * 4, fh + kk * 4, fl + kk * 4, h0, h1, l0, l1);
                        mma3(acc + (2 * p + 1) * 4, fh + kk * 4, fl + kk * 4, h2, h3, l2, l3);
                    }
                }
            }
            fwd_epi(acc, C + 128, stg, g, tig, fh, fl);
            __syncwarp();
            stage_flush(stg, gdw + 128, lane);
            __syncwarp();

            // ---- L3 ----
            float a3[8];
            #pragma unroll
            for (int i = 0; i < 8; ++i) a3[i] = 0.f;
            {
                const uint32_t rb_ = smb + FB_W3H * 2 + lrow * 48 + lcol;
                #pragma unroll
                for (int kk = 0; kk < 4; ++kk) {
                    uint32_t h0, h1, h2, h3, l0, l1, l2, l3;
                    ldmx4(rb_ + kk * 16 * 48, h0, h1, h2, h3);
                    ldmx4(rb_ + kk * 16 * 48 + 3072, l0, l1, l2, l3);
                    mma3(a3 + 0, fh + kk * 4, fl + kk * 4, h0, h1, l0, l1);
                    mma3(a3 + 4, fh + kk * 4, fl + kk * 4, h2, h3, l2, l3);
                }
            }
            float dxv[8];
            dxv[0] = a3[0] + C[192 + d0c];  dxv[1] = a3[1] + C[192 + d0c + 1];
            dxv[2] = a3[2] + C[192 + d0c];  dxv[3] = a3[3] + C[192 + d0c + 1];
            dxv[4] = a3[4] + C[192 + d1c];  dxv[5] = a3[5] + C[192 + d1c + 1];
            dxv[6] = a3[6] + C[192 + d1c];  dxv[7] = a3[7] + C[192 + d1c + 1];

            float dvA = dxv[0] * dxv[0] + dxv[1] * dxv[1] + dxv[4] * dxv[4] + dxv[5] * dxv[5];
            float dvB = dxv[2] * dxv[2] + dxv[3] * dxv[3] + dxv[6] * dxv[6] + dxv[7] * dxv[7];
            dvA += __shfl_xor_sync(0xffffffffu, dvA, 1);
            dvA += __shfl_xor_sync(0xffffffffu, dvA, 2);
            dvB += __shfl_xor_sync(0xffffffffu, dvB, 1);
            dvB += __shfl_xor_sync(0xffffffffu, dvB, 2);

            #pragma unroll
            for (int i = 0; i < 8; ++i) { ksx[i] += wq * dxv[i]; kxp[i] = dxv[i]; }
            ksvA += wq * dvA;
            ksvB += wq * dvB;
        }

        const float scl = hstep * (1.f / 6.f);
        #pragma unroll
        for (int i = 0; i < 8; ++i) xs[i] += scl * ksx[i];
        vA += scl * 0.5f * ksvA;
        vB += scl * 0.5f * ksvB;

        float* os = out + (step + 1) * BATCH * Dd;
        *(float2*)(os + rowA * 16 + d0c) = make_float2(xs[0], xs[1]);
        *(float2*)(os + rowB * 16 + d0c) = make_float2(xs[2], xs[3]);
        *(float2*)(os + rowA * 16 + d1c) = make_float2(xs[4], xs[5]);
        *(float2*)(os + rowB * 16 + d1c) = make_float2(xs[6], xs[7]);
    }

    if (tig == 0) {
        const int base = 3 * BATCH * Dd;
        out[base + BATCH + rowA] = fabsf(vA);
        out[base + BATCH + rowB] = fabsf(vB);
        out[base + 2 * BATCH + rowA] = 0.f;
        out[base + 2 * BATCH + rowB] = 0.f;
    }
}

// ================= tangent kernel (fp16 mma, fused combine, cp.async copy-in) =================
#define TS_TF 4608
#define TS_DV (TS_TF + TF_FLOATS)
#define TS_FLOATS (TS_DV + 64 * 192)
#define TS_BYTES (TS_FLOATS * 4)

__global__ __launch_bounds__(256, 2)
void tangent_kernel(const float* __restrict__ ts, float* __restrict__ out)
{
    extern __shared__ float sm[];
    const int tid = threadIdx.x;
    const int lane = tid & 31;
    const int wid = tid >> 5;

    const int e = blockIdx.x >> 9;
    const int rg = blockIdx.x & 511;
    const int row0 = rg * 64;
    const int tmap[8] = {0, 1, 1, 2, 2, 3, 3, 4};
    const int tt = tmap[e];

    const int stp = e >> 2, stg_i = e & 3;
    const float hstep = ts[stp + 1] - ts[stp];
    const float wrk = (hstep * (1.f / 6.f)) * ((stg_i == 1 || stg_i == 2) ? 2.f : 1.f);

    {
        const uint32_t smb0 = smem_u32(sm);
        const char* bsrc = (const char*)(g_Thf + (size_t)tt * 2 * BP_ELEMS);
        #pragma unroll 4
        for (int i = tid; i < (2 * BP_ELEMS * 2) / 16; i += 256)
            cpa16(smb0 + i * 16, bsrc + i * 16);
        const char* fsrc = (const char*)(g_Tf + tt * TF_FLOATS);
        #pragma unroll 2
        for (int i = tid; i < (TF_FLOATS * 4) / 16; i += 256)
            cpa16(smb0 + TS_TF * 4 + i * 16, fsrc + i * 16);
        const char* dsrc = (const char*)(g_d + ((size_t)e * BATCH + row0) * 192);
        #pragma unroll 4
        for (int i = tid; i < (64 * 192 * 4) / 16; i += 256)
            cpa16(smb0 + TS_DV * 4 + i * 16, dsrc + i * 16);
        cpa_commit_wait();
    }
    __syncthreads();

    const uint32_t smbB = smem_u32(sm);
    const float* M0f = sm + TS_TF;
    const float* M3T = sm + TS_TF + TF_M3T;

    const int g = lane >> 2;
    const int k0 = (lane & 3) * 2;
    const uint32_t lrow = lane & 15, lcol = (lane >> 4) * 16;

    #pragma unroll 1
    for (int rl = 0; rl < 8; ++rl) {
        const int r = wid * 8 + rl;
        const float* d0p = sm + TS_DV + r * 192;
        const float* d1p = d0p + 64;
        const float* d2p = d0p + 128;

        float acc1[32], acc2[32];
        #pragma unroll
        for (int i = 0; i < 32; ++i) { acc1[i] = 0.f; acc2[i] = 0.f; }

        #pragma unroll
        for (int kk = 0; kk < 4; ++kk) {
            const int K = kk * 16;
            // GEMM1: U2 = (M0f .* d0) @ B1
            {
                const float2 dA = *(const float2*)(d0p + K + k0);
                const float2 dB = *(const float2*)(d0p + K + k0 + 8);
                const float2 mA = *(const float2*)(M0f + g * TF_STRIDE + K + k0);
                const float2 mB = *(const float2*)(M0f + (g + 8) * TF_STRIDE + K + k0);
                const float2 mC = *(const float2*)(M0f + g * TF_STRIDE + K + k0 + 8);
                const float2 mD = *(const float2*)(M0f + (g + 8) * TF_STRIDE + K + k0 + 8);
                uint32_t ah[4];
                ah[0] = f16pk(mA.x * dA.x, mA.y * dA.y);
                ah[1] = f16pk(mB.x * dA.x, mB.y * dA.y);
                ah[2] = f16pk(mC.x * dB.x, mC.y * dB.y);
                ah[3] = f16pk(mD.x * dB.x, mD.y * dB.y);
                const uint32_t rowaddr = smbB + (K + lrow) * (BP_STRIDE * 2) + lcol;
                #pragma unroll
                for (int p = 0; p < 4; ++p) {
                    uint32_t h0, h1, h2, h3;
                    ldmx4(rowaddr + p * 32, h0, h1, h2, h3);
                    mma16816h(acc1 + (2 * p) * 4, ah, h0, h1);
                    mma16816h(acc1 + (2 * p + 1) * 4, ah, h2, h3);
                }
            }
            // GEMM2: W = (M3T .* d2) @ B2
            {
                const float2 dA = *(const float2*)(d2p + K + k0);
                const float2 dB = *(const float2*)(d2p + K + k0 + 8);
                const float2 mA = *(const float2*)(M3T + g * TF_STRIDE + K + k0);
                const float2 mB = *(const float2*)(M3T + (g + 8) * TF_STRIDE + K + k0);
                const float2 mC = *(const float2*)(M3T + g * TF_STRIDE + K + k0 + 8);
                const float2 mD = *(const float2*)(M3T + (g + 8) * TF_STRIDE + K + k0 + 8);
                uint32_t ah[4];
                ah[0] = f16pk(mA.x * dA.x, mA.y * dA.y);
                ah[1] = f16pk(mB.x * dA.x, mB.y * dA.y);
                ah[2] = f16pk(mC.x * dB.x, mC.y * dB.y);
                ah[3] = f16pk(mD.x * dB.x, mD.y * dB.y);
                const uint32_t rowaddr = smbB + (K + lrow) * (BP_STRIDE * 2) + lcol + BP_ELEMS * 2;
                #pragma unroll
                for (int p = 0; p < 4; ++p) {
                    uint32_t h0, h1, h2, h3;
                    ldmx4(rowaddr + p * 32, h0, h1, h2, h3);
                    mma16816h(acc2 + (2 * p) * 4, ah, h0, h1);
                    mma16816h(acc2 + (2 * p + 1) * 4, ah, h2, h3);
                }
            }
        }

        // ---- dl = sum U2 .* d1 .* W ----
        float dl = 0.f;
        #pragma unroll
        for (int nt = 0; nt < 8; ++nt) {
            const float2 dp = *(const float2*)(d1p + nt * 8 + k0);
            dl = fmaf(acc1[nt * 4 + 0] * dp.x, acc2[nt * 4 + 0], dl);
            dl = fmaf(acc1[nt * 4 + 1] * dp.y, acc2[nt * 4 + 1], dl);
            dl = fmaf(acc1[nt * 4 + 2] * dp.x, acc2[nt * 4 + 2], dl);
            dl = fmaf(acc1[nt * 4 + 3] * dp.y, acc2[nt * 4 + 3], dl);
        }
        #pragma unroll
        for (int m = 1; m <= 16; m <<= 1)
            dl += __shfl_xor_sync(0xffffffffu, dl, m);
        if (lane == 0)
            atomicAdd(out + 3 * BATCH * Dd + row0 + r, wrk * dl);
    }
}

extern "C" void kernel_launch(void* const* d_in, const int* in_sizes, int n_in,
                              void* d_out, int out_size) {
    const float* ts  = (const float*)d_in[0];
    const float* x0  = (const float*)d_in[1];
    const float* W0  = (const float*)d_in[2];
    const float* b0  = (const float*)d_in[3];
    const float* g0  = (const float*)d_in[4];
    const float* gb0 = (const float*)d_in[5];
    const float* hb0 = (const float*)d_in[6];
    const float* W1  = (const float*)d_in[7];
    const float* b1  = (const float*)d_in[8];
    const float* g1  = (const float*)d_in[9];
    const float* gb1 = (const float*)d_in[10];
    const float* hb1 = (const float*)d_in[11];
    const float* W2  = (const float*)d_in[12];
    const float* b2  = (const float*)d_in[13];
    const float* g2  = (const float*)d_in[14];
    const float* gb2 = (const float*)d_in[15];
    const float* hb2 = (const float*)d_in[16];
    const float* W3  = (const float*)d_in[17];
    const float* b3  = (const float*)d_in[18];
    const float* g3  = (const float*)d_in[19];
    const float* gb3 = (const float*)d_in[20];
    const float* hb3 = (const float*)d_in[21];
    float* out = (float*)d_out;

    build_kernel<<<NT * 8, 256>>>(ts,
        W0, b0, g0, gb0, hb0,
        W1, b1, g1, gb1, hb1,
        W2, b2, g2, gb2, hb2,
        W3, b3, g3, gb3, hb3);

    cudaFuncSetAttribute(forward_kernel, cudaFuncAttributeMaxDynamicSharedMemorySize, FWD_SMEM);
    forward_kernel<<<BATCH / FROWS, FNT, FWD_SMEM>>>(ts, x0, out);

    cudaFuncSetAttribute(tangent_kernel, cudaFuncAttributeMaxDynamicSharedMemorySize, TS_BYTES);
    tangent_kernel<<<8 * 512, 256, TS_BYTES>>>(ts, out);
}